// round 1
// baseline (speedup 1.0000x reference)
#include <cuda_runtime.h>
#include <math.h>
#include <stdint.h>

// Problem constants
#define Bc 4
#define Sc 512
#define Dc 512
#define Hc 4
#define Vc 32000
#define Rc (Bc*Sc)    // 2048 query rows
#define HDc (Hc*Dc)   // 2048
#define NSPLIT 8

// ---------------- scratch (device globals: allocation-free) ----------------
__device__ float d_e[Rc*Dc];                     // LN(wte[x])
__device__ float d_p[(Sc+1)*Dc];                 // LN(wpe)
__device__ float d_Q[Hc*Sc*Dc];
__device__ float d_Kt[Hc*Sc*Dc];
__device__ float d_krn[Hc*Sc*Sc];
__device__ float d_fk[Rc*Dc];
__device__ float d_scores[(size_t)Rc*Vc];        // 262 MB
__device__ float d_vm[Rc*Dc];
__device__ float d_delta[Rc*HDc];
__device__ float d_part[(size_t)NSPLIT*Rc*Dc];   // split-K partials
__device__ float d_cmeanp[32*Dc];
__device__ float d_cmean[Dc];
__device__ float d_last[Bc*Dc];

// ---------------- epilogue modes ----------------
#define EPI_NONE 0
#define EPI_ATTN 1   // *scale, clip +-10, causal mask (col>row -> -inf)
#define EPI_COEF 2   // * 1/(1+row)

#define BM 128
#define BN 128
#define BK 8

// C = op(A[MxK]) @ op(B) (+C if beta)
// zmode 0: batched — z decomposed as lo=z%zdiv, hi=z/zdiv, strides applied
// zmode 1: split-K — z picks K chunk, C offset by z*M*ldc (partial buffers)
__global__ void __launch_bounds__(256)
sgemm_nn(int M, int N, int K,
         const float* __restrict__ A, int lda,
         const float* __restrict__ B, int ldb,
         float* __restrict__ C, int ldc,
         int beta, int epi, float scale,
         int zmode, int zdiv,
         long sAlo, long sAhi, long sBlo, long sBhi, long sClo, long sChi)
{
    __shared__ float As[BK][BM];
    __shared__ float Bs[BK][BN];
    int z = blockIdx.z;
    int kBeg = 0, kEnd = K;
    if (zmode == 1) {
        int Kc = K / gridDim.z;
        kBeg = z * Kc; kEnd = kBeg + Kc;
        C += (size_t)z * M * ldc;
    } else {
        int lo = z % zdiv, hi = z / zdiv;
        A += (size_t)lo * sAlo + (size_t)hi * sAhi;
        B += (size_t)lo * sBlo + (size_t)hi * sBhi;
        C += (size_t)lo * sClo + (size_t)hi * sChi;
    }
    const int tid = threadIdx.x;
    const int tx = tid & 15, ty = tid >> 4;
    const int rowBase = blockIdx.y * BM, colBase = blockIdx.x * BN;
    const int aRow = tid >> 1,  aCol = (tid & 1) << 2;
    const int bRow = tid >> 5,  bCol = (tid & 31) << 2;

    float acc[8][8];
#pragma unroll
    for (int i = 0; i < 8; i++)
#pragma unroll
        for (int j = 0; j < 8; j++) acc[i][j] = 0.f;

    for (int k0 = kBeg; k0 < kEnd; k0 += BK) {
        float4 av = *(const float4*)(A + (size_t)(rowBase + aRow) * lda + k0 + aCol);
        As[aCol+0][aRow] = av.x; As[aCol+1][aRow] = av.y;
        As[aCol+2][aRow] = av.z; As[aCol+3][aRow] = av.w;
        float4 bv = *(const float4*)(B + (size_t)(k0 + bRow) * ldb + colBase + bCol);
        *(float4*)&Bs[bRow][bCol] = bv;
        __syncthreads();
#pragma unroll
        for (int kk = 0; kk < BK; kk++) {
            float a[8], b[8];
            *(float4*)&a[0] = *(const float4*)&As[kk][ty*8];
            *(float4*)&a[4] = *(const float4*)&As[kk][ty*8+4];
            *(float4*)&b[0] = *(const float4*)&Bs[kk][tx*8];
            *(float4*)&b[4] = *(const float4*)&Bs[kk][tx*8+4];
#pragma unroll
            for (int i = 0; i < 8; i++)
#pragma unroll
                for (int j = 0; j < 8; j++) acc[i][j] = fmaf(a[i], b[j], acc[i][j]);
        }
        __syncthreads();
    }
#pragma unroll
    for (int i = 0; i < 8; i++) {
        int r = rowBase + ty*8 + i;
#pragma unroll
        for (int j = 0; j < 8; j++) {
            int c = colBase + tx*8 + j;
            float v = acc[i][j];
            if (epi == EPI_ATTN) {
                v *= scale;
                v = fminf(10.f, fmaxf(-10.f, v));
                if (c > r) v = -INFINITY;
            } else if (epi == EPI_COEF) {
                v *= 1.0f / (1.0f + (float)r);
            }
            size_t ci = (size_t)r * ldc + c;
            if (beta) C[ci] += v; else C[ci] = v;
        }
    }
}

// C = A[MxK] @ B[NxK]^T
__global__ void __launch_bounds__(256)
sgemm_nt(int M, int N, int K,
         const float* __restrict__ A, int lda,
         const float* __restrict__ B, int ldb,
         float* __restrict__ C, int ldc,
         int beta, int epi, float scale,
         int zdiv,
         long sAlo, long sAhi, long sBlo, long sBhi, long sClo, long sChi)
{
    __shared__ float As[BK][BM];
    __shared__ float Bs[BK][BN];
    int z = blockIdx.z;
    {
        int lo = z % zdiv, hi = z / zdiv;
        A += (size_t)lo * sAlo + (size_t)hi * sAhi;
        B += (size_t)lo * sBlo + (size_t)hi * sBhi;
        C += (size_t)lo * sClo + (size_t)hi * sChi;
    }
    const int tid = threadIdx.x;
    const int tx = tid & 15, ty = tid >> 4;
    const int rowBase = blockIdx.y * BM, colBase = blockIdx.x * BN;
    const int aRow = tid >> 1, aCol = (tid & 1) << 2;
    const int bN   = tid >> 1, bK   = (tid & 1) << 2;

    float acc[8][8];
#pragma unroll
    for (int i = 0; i < 8; i++)
#pragma unroll
        for (int j = 0; j < 8; j++) acc[i][j] = 0.f;

    for (int k0 = 0; k0 < K; k0 += BK) {
        float4 av = *(const float4*)(A + (size_t)(rowBase + aRow) * lda + k0 + aCol);
        As[aCol+0][aRow] = av.x; As[aCol+1][aRow] = av.y;
        As[aCol+2][aRow] = av.z; As[aCol+3][aRow] = av.w;
        float4 bv = *(const float4*)(B + (size_t)(colBase + bN) * ldb + k0 + bK);
        Bs[bK+0][bN] = bv.x; Bs[bK+1][bN] = bv.y;
        Bs[bK+2][bN] = bv.z; Bs[bK+3][bN] = bv.w;
        __syncthreads();
#pragma unroll
        for (int kk = 0; kk < BK; kk++) {
            float a[8], b[8];
            *(float4*)&a[0] = *(const float4*)&As[kk][ty*8];
            *(float4*)&a[4] = *(const float4*)&As[kk][ty*8+4];
            *(float4*)&b[0] = *(const float4*)&Bs[kk][tx*8];
            *(float4*)&b[4] = *(const float4*)&Bs[kk][tx*8+4];
#pragma unroll
            for (int i = 0; i < 8; i++)
#pragma unroll
                for (int j = 0; j < 8; j++) acc[i][j] = fmaf(a[i], b[j], acc[i][j]);
        }
        __syncthreads();
    }
#pragma unroll
    for (int i = 0; i < 8; i++) {
        int r = rowBase + ty*8 + i;
#pragma unroll
        for (int j = 0; j < 8; j++) {
            int c = colBase + tx*8 + j;
            float v = acc[i][j];
            if (epi == EPI_ATTN) {
                v *= scale;
                v = fminf(10.f, fmaxf(-10.f, v));
                if (c > r) v = -INFINITY;
            } else if (epi == EPI_COEF) {
                v *= 1.0f / (1.0f + (float)r);
            }
            size_t ci = (size_t)r * ldc + c;
            if (beta) C[ci] += v; else C[ci] = v;
        }
    }
}

// ---------------- reductions / elementwise ----------------
__device__ __forceinline__ float warpSum(float v) {
#pragma unroll
    for (int o = 16; o; o >>= 1) v += __shfl_xor_sync(0xffffffffu, v, o);
    return v;
}
__device__ __forceinline__ float warpMax(float v) {
#pragma unroll
    for (int o = 16; o; o >>= 1) v = fmaxf(v, __shfl_xor_sync(0xffffffffu, v, o));
    return v;
}

// LayerNorm over rows of length 512 (256 threads, 2 elems/thread).
// src row = base + (idx ? idx[row] : row) * rowStride
__global__ void ln_rows(const float* __restrict__ base, const int* __restrict__ idx,
                        const float* __restrict__ g, float* __restrict__ dst,
                        long rowStride)
{
    int row = blockIdx.x;
    const float* src = base + (idx ? (size_t)idx[row] * rowStride
                                   : (size_t)row * rowStride);
    int tid = threadIdx.x, lane = tid & 31, w = tid >> 5;
    __shared__ float sb[8];
    float v0 = src[tid], v1 = src[tid + 256];
    float s = warpSum(v0 + v1);
    if (lane == 0) sb[w] = s;
    __syncthreads();
    float tot = 0.f;
#pragma unroll
    for (int i = 0; i < 8; i++) tot += sb[i];
    float m = tot * (1.f / 512.f);
    float a0 = v0 - m, a1 = v1 - m;
    __syncthreads();
    float q = warpSum(a0*a0 + a1*a1);
    if (lane == 0) sb[w] = q;
    __syncthreads();
    float var = 0.f;
#pragma unroll
    for (int i = 0; i < 8; i++) var += sb[i];
    var *= (1.f / 512.f);
    float inv = rsqrtf(var + 1e-5f);
    float* dr = dst + (size_t)row * 512;
    dr[tid]       = a0 * inv * g[tid];
    dr[tid + 256] = a1 * inv * g[tid + 256];
}

// in-place row softmax (handles -inf entries)
__global__ void softmax_rows(float* __restrict__ data, int ncol)
{
    float* row = data + (size_t)blockIdx.x * ncol;
    __shared__ float sb[8];
    int tid = threadIdx.x, lane = tid & 31, w = tid >> 5;
    float m = -INFINITY;
    for (int c = tid; c < ncol; c += 256) m = fmaxf(m, row[c]);
    m = warpMax(m);
    if (lane == 0) sb[w] = m;
    __syncthreads();
    float bm = sb[0];
#pragma unroll
    for (int i = 1; i < 8; i++) bm = fmaxf(bm, sb[i]);
    __syncthreads();
    float s = 0.f;
    for (int c = tid; c < ncol; c += 256) s += __expf(row[c] - bm);
    s = warpSum(s);
    if (lane == 0) sb[w] = s;
    __syncthreads();
    float bs = 0.f;
#pragma unroll
    for (int i = 0; i < 8; i++) bs += sb[i];
    float inv = 1.f / bs;
    for (int c = tid; c < ncol; c += 256) row[c] = __expf(row[c] - bm) * inv;
}

// column mean of wte (layer-0 shortcut): partial over 32 v-chunks, then reduce
__global__ void col_mean_part(const float* __restrict__ wte)
{
    int d = blockIdx.x * 128 + threadIdx.x;
    int z = blockIdx.y;                      // 0..31, 1000 rows each
    float s = 0.f;
    int v0 = z * 1000;
    for (int v = v0; v < v0 + 1000; v++) s += wte[(size_t)v * Dc + d];
    d_cmeanp[z * Dc + d] = s;
}
__global__ void col_mean_reduce()
{
    int d = blockIdx.x * 128 + threadIdx.x;
    float s = 0.f;
#pragma unroll
    for (int z = 0; z < 32; z++) s += d_cmeanp[z * Dc + d];
    d_cmean[d] = s * (1.f / 32000.f);
}

// Vm = e - colmean(wte)   (layer 0)
__global__ void vm_mean_k()
{
    int i = blockIdx.x * 256 + threadIdx.x;   // grid covers Rc*Dc exactly
    d_vm[i] = d_e[i] - d_cmean[i & (Dc - 1)];
}
// Vm = e - sum(split-K partials)   (layers 1..3)
__global__ void vm_parts_k()
{
    int i = blockIdx.x * 256 + threadIdx.x;
    float s = 0.f;
#pragma unroll
    for (int z = 0; z < NSPLIT; z++) s += d_part[(size_t)z * (Rc*Dc) + i];
    d_vm[i] = d_e[i] - s;
}

// logits[b, v] = dot(last[b], wte[v]); one warp per output
__global__ void logits_kernel(const float* __restrict__ last,
                              const float* __restrict__ wte,
                              float* __restrict__ out)
{
    int w = threadIdx.x >> 5, lane = threadIdx.x & 31;
    int v = blockIdx.x * 8 + w;
    int b = blockIdx.y;
    const float* q = last + b * 512;
    const float* wr = wte + (size_t)v * 512;
    float s = 0.f;
#pragma unroll
    for (int d = lane; d < 512; d += 32) s = fmaf(q[d], wr[d], s);
    s = warpSum(s);
    if (lane == 0) out[(size_t)b * Vc + v] = s;
}

// ---------------- launch ----------------
extern "C" void kernel_launch(void* const* d_in, const int* in_sizes, int n_in,
                              void* d_out, int out_size)
{
    const int*   x   = (const int*)  d_in[0];
    const float* wte = (const float*)d_in[1];
    const float* wpe = (const float*)d_in[2];
    const float* g_e = (const float*)d_in[3];
    const float* g_p = (const float*)d_in[4];
    const float* g_f = (const float*)d_in[5];
    const float* W_q = (const float*)d_in[6];
    const float* W_k = (const float*)d_in[7];
    const float* W_o = (const float*)d_in[8];
    float* out = (float*)d_out;

    float *e, *p, *Q, *Kt, *krn, *fk, *sc, *vm, *delta, *part, *last;
    cudaGetSymbolAddress((void**)&e,     d_e);
    cudaGetSymbolAddress((void**)&p,     d_p);
    cudaGetSymbolAddress((void**)&Q,     d_Q);
    cudaGetSymbolAddress((void**)&Kt,    d_Kt);
    cudaGetSymbolAddress((void**)&krn,   d_krn);
    cudaGetSymbolAddress((void**)&fk,    d_fk);
    cudaGetSymbolAddress((void**)&sc,    d_scores);
    cudaGetSymbolAddress((void**)&vm,    d_vm);
    cudaGetSymbolAddress((void**)&delta, d_delta);
    cudaGetSymbolAddress((void**)&part,  d_part);
    cudaGetSymbolAddress((void**)&last,  d_last);

    const long SD = (long)Sc * Dc;       // 262144
    const long SS = (long)Sc * Sc;
    const float attnScale = 0.044194173824159216f;  // 1/sqrt(512)

    // embeddings + positional LN
    ln_rows<<<Rc,   256>>>(wte, x, g_e, e, (long)Dc);
    ln_rows<<<Sc+1, 256>>>(wpe, nullptr, g_p, p, (long)Dc);

    // column mean of wte (layer-0 ex_wte)
    col_mean_part<<<dim3(4, 32), 128>>>(wte);
    col_mean_reduce<<<4, 128>>>();

    // Q[h] = p[1:] @ W_q[h] ; K[h] = p[:-1] @ W_k[h]  (batched over h)
    sgemm_nn<<<dim3(4,4,4),256>>>(Sc,Dc,Dc, p+Dc,Dc, W_q,Dc, Q,Dc,
                                  0, EPI_NONE, 0.f, 0, 1,
                                  0,0, 0,(long)Dc*Dc, 0,SD);
    sgemm_nn<<<dim3(4,4,4),256>>>(Sc,Dc,Dc, p,Dc, W_k,Dc, Kt,Dc,
                                  0, EPI_NONE, 0.f, 0, 1,
                                  0,0, 0,(long)Dc*Dc, 0,SD);
    // krn[h] = causal-softmax(clip(Q K^T / sqrt(D)))
    sgemm_nt<<<dim3(4,4,4),256>>>(Sc,Sc,Dc, Q,Dc, Kt,Dc, krn,Sc,
                                  0, EPI_ATTN, attnScale, 1,
                                  0,SD, 0,SD, 0,SS);
    softmax_rows<<<Hc*Sc, 256>>>(krn, Sc);

    cudaMemsetAsync(fk, 0, (size_t)Rc * Dc * sizeof(float), 0);

    for (int layer = 0; layer < 4; layer++) {
        if (layer == 0) {
            vm_mean_k<<<Rc*Dc/256, 256>>>();
        } else {
            // scores[r, v] = f_k[r] . wte[v]
            sgemm_nt<<<dim3(Vc/128, Rc/128, 1),256>>>(Rc,Vc,Dc, fk,Dc, wte,Dc, sc,Vc,
                                                      0, EPI_NONE, 0.f, 1,
                                                      0,0,0,0,0,0);
            softmax_rows<<<Rc, 256>>>(sc, Vc);
            // ex_wte = P @ wte via 8-way split-K into partials
            sgemm_nn<<<dim3(Dc/128, Rc/128, NSPLIT),256>>>(Rc,Dc,Vc, sc,Vc, wte,Dc, part,Dc,
                                                           0, EPI_NONE, 0.f, 1, 1,
                                                           0,0,0,0,0,0);
            vm_parts_k<<<Rc*Dc/256, 256>>>();
        }
        // delta[b,:,h,:] = coef * (krn[h] @ Vm[b])  — batched z = b*4 + h
        sgemm_nn<<<dim3(4,4,16),256>>>(Sc,Dc,Sc, krn,Sc, vm,Dc, delta,HDc,
                                       0, EPI_COEF, 0.f, 0, 4,
                                       SS, 0,          // A: + h*S*S
                                       0, SD,          // B: + b*S*D
                                       (long)Dc, (long)Sc*HDc); // C: + h*D + b*S*HD
        // f_k += delta_flat @ W_o^T
        sgemm_nt<<<dim3(Dc/128, Rc/128, 1),256>>>(Rc,Dc,HDc, delta,HDc, W_o,HDc, fk,Dc,
                                                  1, EPI_NONE, 0.f, 1,
                                                  0,0,0,0,0,0);
    }

    // final LN on last position only, then logits
    ln_rows<<<Bc, 256>>>(fk + (size_t)(Sc-1)*Dc, nullptr, g_f, last, (long)Sc*Dc);
    logits_kernel<<<dim3(Vc/8, Bc), 256>>>(last, wte, out);
}

// round 3
// speedup vs baseline: 3.4091x; 3.4091x over previous
#include <cuda_runtime.h>
#include <cuda_bf16.h>
#include <math.h>
#include <stdint.h>

// Problem constants
#define Bc 4
#define Sc 512
#define Dc 512
#define Hc 4
#define Vc 32000
#define Rc (Bc*Sc)    // 2048 query rows
#define HDc (Hc*Dc)   // 2048
#define NSPLIT 10

// ---------------- scratch (device globals: allocation-free) ----------------
__device__ float d_e[Rc*Dc];                     // LN(wte[x])
__device__ float d_p[(Sc+1)*Dc];                 // LN(wpe)
__device__ float d_Q[Hc*Sc*Dc];
__device__ float d_Kt[Hc*Sc*Dc];
__device__ float d_krn[Hc*Sc*Sc];
__device__ float d_fk[Rc*Dc];
__device__ float d_vm[Rc*Dc];
__device__ float d_delta[Rc*HDc];
__device__ float d_part[(size_t)NSPLIT*Rc*Dc];   // split-K fp32 partials (num)
__device__ float d_cmeanp[32*Dc];
__device__ float d_cmean[Dc];
__device__ float d_last[Bc*Dc];
// bf16 path
__device__ __nv_bfloat16 d_E[(size_t)Rc*Vc];         // exp(scores), bf16 (131MB)
__device__ __nv_bfloat16 d_wte_bf[(size_t)Vc*Dc];    // wte bf16 [v,d]
__device__ __nv_bfloat16 d_wteT_bf[(size_t)Dc*Vc];   // wte bf16 transposed [d,v]
__device__ __nv_bfloat16 d_fk_bf[Rc*Dc];
__device__ float d_denp[(Vc/128)*Rc];                // per-x-block row sums of E
__device__ float d_den[Rc];

// =================== PTX helpers ===================
__device__ __forceinline__ uint32_t smem_u32(const void* p){
    uint32_t a;
    asm("{ .reg .u64 t; cvta.to.shared.u64 t, %1; cvt.u32.u64 %0, t; }":"=r"(a):"l"(p));
    return a;
}
__device__ __forceinline__ void cp16(uint32_t s, const void* g){
    asm volatile("cp.async.cg.shared.global [%0], [%1], 16;"::"r"(s),"l"(g));
}
__device__ __forceinline__ void cp_commit(){ asm volatile("cp.async.commit_group;"); }
template<int N> __device__ __forceinline__ void cp_wait(){ asm volatile("cp.async.wait_group %0;"::"n"(N)); }

__device__ __forceinline__ void ldm_x4(uint32_t& r0,uint32_t& r1,uint32_t& r2,uint32_t& r3,uint32_t addr){
    asm volatile("ldmatrix.sync.aligned.m8n8.x4.shared.b16 {%0,%1,%2,%3}, [%4];"
      : "=r"(r0),"=r"(r1),"=r"(r2),"=r"(r3) : "r"(addr));
}
__device__ __forceinline__ void mma16816(float* c, uint32_t a0,uint32_t a1,uint32_t a2,uint32_t a3,
                                         uint32_t b0,uint32_t b1){
    asm volatile("mma.sync.aligned.m16n8k16.row.col.f32.bf16.bf16.f32 "
      "{%0,%1,%2,%3}, {%4,%5,%6,%7}, {%8,%9}, {%0,%1,%2,%3};"
      : "+f"(c[0]),"+f"(c[1]),"+f"(c[2]),"+f"(c[3])
      : "r"(a0),"r"(a1),"r"(a2),"r"(a3),"r"(b0),"r"(b1));
}

// =================== bf16 HMMA vocab GEMM ===================
// C[128,128] per CTA = A(128 x K) @ B(128 x K)^T, both K-major bf16.
// MODE 0: C -> exp(min(C,70)): bf16 Eout (row stride Vc) + row-sum partials denPart.
// MODE 1: C -> fp32 partial buffer z (row stride Dc), split-K over blockIdx.z.
#define PITCH 80           // 32 bf16 data + 8 pad, conflict-free for ldmatrix
#define ABUF  10240        // 128 * 80
#define TBUF  20480        // A + B per stage

template<int MODE>
__global__ void __launch_bounds__(256)
mma_vocab(const __nv_bfloat16* __restrict__ A, long lda,
          const __nv_bfloat16* __restrict__ B, long ldb,
          int kTiles,
          __nv_bfloat16* __restrict__ Eout, float* __restrict__ denPart,
          float* __restrict__ Pout)
{
    __shared__ char smem[2*TBUF];                 // 40 KB double-buffered
    const uint32_t sb = smem_u32(smem);
    const int tid = threadIdx.x, lane = tid & 31, wid = tid >> 5;
    const int wm = wid & 1, wn = wid >> 1;        // 2 x 4 warp grid
    const int wmBase = wm * 64, wnBase = wn * 32;
    const int rowBase = blockIdx.y << 7, colBase = blockIdx.x << 7;
    const long k0base = (long)blockIdx.z * kTiles * 32;

    float acc[4][4][4];
#pragma unroll
    for (int mt = 0; mt < 4; mt++)
#pragma unroll
        for (int nt = 0; nt < 4; nt++)
#pragma unroll
            for (int q = 0; q < 4; q++) acc[mt][nt][q] = 0.f;

    // ldmatrix lane address components
    const int ar = lane & 15;                     // A row within 16
    const int akof = (lane >> 4) * 8;             // A k offset 0/8
    const int bn = (lane & 7) + ((lane & 16) ? 8 : 0);   // B n within 16
    const int bkof = ((lane >> 3) & 1) * 8;       // B k offset 0/8

    // tile loader: 128 rows x 64B each for A and B
    auto load = [&](int buf, long k0){
        uint32_t base = sb + buf*TBUF;
#pragma unroll
        for (int i = 0; i < 2; i++){
            int c = tid + i*256; int r = c >> 2, s = c & 3;
            cp16(base + r*PITCH + s*16, A + (size_t)(rowBase + r)*lda + k0 + s*8);
        }
#pragma unroll
        for (int i = 0; i < 2; i++){
            int c = tid + i*256; int r = c >> 2, s = c & 3;
            cp16(base + ABUF + r*PITCH + s*16, B + (size_t)(colBase + r)*ldb + k0 + s*8);
        }
        cp_commit();
    };

    load(0, k0base);
    for (int t = 0; t < kTiles; t++){
        if (t + 1 < kTiles){ load((t+1)&1, k0base + (long)(t+1)*32); cp_wait<1>(); }
        else cp_wait<0>();
        __syncthreads();
        uint32_t base = sb + (t&1)*TBUF;
#pragma unroll
        for (int kk = 0; kk < 2; kk++){
            uint32_t a[4][4], b[2][4];
            uint32_t aCol = (uint32_t)((kk*16 + akof) * 2);
            uint32_t bCol = (uint32_t)((kk*16 + bkof) * 2);
#pragma unroll
            for (int mt = 0; mt < 4; mt++)
                ldm_x4(a[mt][0], a[mt][1], a[mt][2], a[mt][3],
                       base + (uint32_t)(wmBase + mt*16 + ar)*PITCH + aCol);
#pragma unroll
            for (int j = 0; j < 2; j++)
                ldm_x4(b[j][0], b[j][1], b[j][2], b[j][3],
                       base + ABUF + (uint32_t)(wnBase + j*16 + bn)*PITCH + bCol);
#pragma unroll
            for (int mt = 0; mt < 4; mt++)
#pragma unroll
                for (int nt = 0; nt < 4; nt++)
                    mma16816(acc[mt][nt], a[mt][0], a[mt][1], a[mt][2], a[mt][3],
                             b[nt>>1][(nt&1)*2], b[nt>>1][(nt&1)*2 + 1]);
        }
        __syncthreads();
    }

    // epilogue: thread owns rows r0 = wmBase+mt*16+lane/4, r1 = r0+8,
    // cols wnBase + nt*8 + (lane&3)*2 (+1)
    if (MODE == 0){
        float* denm = (float*)smem;               // [128][4] cross-warp reduce
        int cq = (lane & 3) * 2;
#pragma unroll
        for (int mt = 0; mt < 4; mt++){
            int lr0 = wmBase + mt*16 + (lane >> 2);
            int r0 = rowBase + lr0;
            float s0 = 0.f, s1 = 0.f;
#pragma unroll
            for (int nt = 0; nt < 4; nt++){
                int col = colBase + wnBase + nt*8 + cq;
                float e0 = __expf(fminf(acc[mt][nt][0], 70.f));
                float e1 = __expf(fminf(acc[mt][nt][1], 70.f));
                float e2 = __expf(fminf(acc[mt][nt][2], 70.f));
                float e3 = __expf(fminf(acc[mt][nt][3], 70.f));
                s0 += e0 + e1; s1 += e2 + e3;
                __nv_bfloat162 p0 = __float22bfloat162_rn(make_float2(e0, e1));
                __nv_bfloat162 p1 = __float22bfloat162_rn(make_float2(e2, e3));
                *(__nv_bfloat162*)(Eout + (size_t)r0*Vc + col) = p0;
                *(__nv_bfloat162*)(Eout + (size_t)(r0+8)*Vc + col) = p1;
            }
            s0 += __shfl_xor_sync(0xffffffffu, s0, 1);
            s0 += __shfl_xor_sync(0xffffffffu, s0, 2);
            s1 += __shfl_xor_sync(0xffffffffu, s1, 1);
            s1 += __shfl_xor_sync(0xffffffffu, s1, 2);
            if ((lane & 3) == 0){
                denm[lr0*4 + wn] = s0;
                denm[(lr0+8)*4 + wn] = s1;
            }
        }
        __syncthreads();
        if (tid < 128){
            float d = denm[tid*4] + denm[tid*4+1] + denm[tid*4+2] + denm[tid*4+3];
            denPart[(size_t)blockIdx.x * Rc + rowBase + tid] = d;
        }
    } else {
        float* dst = Pout + (size_t)blockIdx.z * ((size_t)Rc*Dc);
        int cq = (lane & 3) * 2;
#pragma unroll
        for (int mt = 0; mt < 4; mt++){
            int r0 = rowBase + wmBase + mt*16 + (lane >> 2);
#pragma unroll
            for (int nt = 0; nt < 4; nt++){
                int col = colBase + wnBase + nt*8 + cq;
                *(float2*)(dst + (size_t)r0*Dc + col) =
                    make_float2(acc[mt][nt][0], acc[mt][nt][1]);
                *(float2*)(dst + (size_t)(r0+8)*Dc + col) =
                    make_float2(acc[mt][nt][2], acc[mt][nt][3]);
            }
        }
    }
}

// =================== fp32 SGEMM (small GEMMs) ===================
#define EPI_NONE 0
#define EPI_ATTN 1
#define EPI_COEF 2
#define BM 128
#define BN 128
#define BK 8

__global__ void __launch_bounds__(256)
sgemm_nn(int M, int N, int K,
         const float* __restrict__ A, int lda,
         const float* __restrict__ B, int ldb,
         float* __restrict__ C, int ldc,
         int beta, int epi, float scale,
         int zdiv,
         long sAlo, long sAhi, long sBlo, long sBhi, long sClo, long sChi)
{
    __shared__ float As[BK][BM];
    __shared__ float Bs[BK][BN];
    int z = blockIdx.z;
    {
        int lo = z % zdiv, hi = z / zdiv;
        A += (size_t)lo * sAlo + (size_t)hi * sAhi;
        B += (size_t)lo * sBlo + (size_t)hi * sBhi;
        C += (size_t)lo * sClo + (size_t)hi * sChi;
    }
    const int tid = threadIdx.x;
    const int tx = tid & 15, ty = tid >> 4;
    const int rowBase = blockIdx.y * BM, colBase = blockIdx.x * BN;
    const int aRow = tid >> 1,  aCol = (tid & 1) << 2;
    const int bRow = tid >> 5,  bCol = (tid & 31) << 2;

    float acc[8][8];
#pragma unroll
    for (int i = 0; i < 8; i++)
#pragma unroll
        for (int j = 0; j < 8; j++) acc[i][j] = 0.f;

    for (int k0 = 0; k0 < K; k0 += BK) {
        float4 av = *(const float4*)(A + (size_t)(rowBase + aRow) * lda + k0 + aCol);
        As[aCol+0][aRow] = av.x; As[aCol+1][aRow] = av.y;
        As[aCol+2][aRow] = av.z; As[aCol+3][aRow] = av.w;
        float4 bv = *(const float4*)(B + (size_t)(k0 + bRow) * ldb + colBase + bCol);
        *(float4*)&Bs[bRow][bCol] = bv;
        __syncthreads();
#pragma unroll
        for (int kk = 0; kk < BK; kk++) {
            float a[8], b[8];
            *(float4*)&a[0] = *(const float4*)&As[kk][ty*8];
            *(float4*)&a[4] = *(const float4*)&As[kk][ty*8+4];
            *(float4*)&b[0] = *(const float4*)&Bs[kk][tx*8];
            *(float4*)&b[4] = *(const float4*)&Bs[kk][tx*8+4];
#pragma unroll
            for (int i = 0; i < 8; i++)
#pragma unroll
                for (int j = 0; j < 8; j++) acc[i][j] = fmaf(a[i], b[j], acc[i][j]);
        }
        __syncthreads();
    }
#pragma unroll
    for (int i = 0; i < 8; i++) {
        int r = rowBase + ty*8 + i;
#pragma unroll
        for (int j = 0; j < 8; j++) {
            int c = colBase + tx*8 + j;
            float v = acc[i][j];
            if (epi == EPI_ATTN) {
                v *= scale;
                v = fminf(10.f, fmaxf(-10.f, v));
                if (c > r) v = -INFINITY;
            } else if (epi == EPI_COEF) {
                v *= 1.0f / (1.0f + (float)r);
            }
            size_t ci = (size_t)r * ldc + c;
            if (beta) C[ci] += v; else C[ci] = v;
        }
    }
}

__global__ void __launch_bounds__(256)
sgemm_nt(int M, int N, int K,
         const float* __restrict__ A, int lda,
         const float* __restrict__ B, int ldb,
         float* __restrict__ C, int ldc,
         int beta, int epi, float scale,
         int zdiv,
         long sAlo, long sAhi, long sBlo, long sBhi, long sClo, long sChi)
{
    __shared__ float As[BK][BM];
    __shared__ float Bs[BK][BN];
    int z = blockIdx.z;
    {
        int lo = z % zdiv, hi = z / zdiv;
        A += (size_t)lo * sAlo + (size_t)hi * sAhi;
        B += (size_t)lo * sBlo + (size_t)hi * sBhi;
        C += (size_t)lo * sClo + (size_t)hi * sChi;
    }
    const int tid = threadIdx.x;
    const int tx = tid & 15, ty = tid >> 4;
    const int rowBase = blockIdx.y * BM, colBase = blockIdx.x * BN;
    const int aRow = tid >> 1, aCol = (tid & 1) << 2;
    const int bN   = tid >> 1, bK   = (tid & 1) << 2;

    float acc[8][8];
#pragma unroll
    for (int i = 0; i < 8; i++)
#pragma unroll
        for (int j = 0; j < 8; j++) acc[i][j] = 0.f;

    for (int k0 = 0; k0 < K; k0 += BK) {
        float4 av = *(const float4*)(A + (size_t)(rowBase + aRow) * lda + k0 + aCol);
        As[aCol+0][aRow] = av.x; As[aCol+1][aRow] = av.y;
        As[aCol+2][aRow] = av.z; As[aCol+3][aRow] = av.w;
        float4 bv = *(const float4*)(B + (size_t)(colBase + bN) * ldb + k0 + bK);
        Bs[bK+0][bN] = bv.x; Bs[bK+1][bN] = bv.y;
        Bs[bK+2][bN] = bv.z; Bs[bK+3][bN] = bv.w;
        __syncthreads();
#pragma unroll
        for (int kk = 0; kk < BK; kk++) {
            float a[8], b[8];
            *(float4*)&a[0] = *(const float4*)&As[kk][ty*8];
            *(float4*)&a[4] = *(const float4*)&As[kk][ty*8+4];
            *(float4*)&b[0] = *(const float4*)&Bs[kk][tx*8];
            *(float4*)&b[4] = *(const float4*)&Bs[kk][tx*8+4];
#pragma unroll
            for (int i = 0; i < 8; i++)
#pragma unroll
                for (int j = 0; j < 8; j++) acc[i][j] = fmaf(a[i], b[j], acc[i][j]);
        }
        __syncthreads();
    }
#pragma unroll
    for (int i = 0; i < 8; i++) {
        int r = rowBase + ty*8 + i;
#pragma unroll
        for (int j = 0; j < 8; j++) {
            int c = colBase + tx*8 + j;
            float v = acc[i][j];
            if (epi == EPI_ATTN) {
                v *= scale;
                v = fminf(10.f, fmaxf(-10.f, v));
                if (c > r) v = -INFINITY;
            } else if (epi == EPI_COEF) {
                v *= 1.0f / (1.0f + (float)r);
            }
            size_t ci = (size_t)r * ldc + c;
            if (beta) C[ci] += v; else C[ci] = v;
        }
    }
}

// ---------------- reductions / elementwise ----------------
__device__ __forceinline__ float warpSum(float v) {
#pragma unroll
    for (int o = 16; o; o >>= 1) v += __shfl_xor_sync(0xffffffffu, v, o);
    return v;
}
__device__ __forceinline__ float warpMax(float v) {
#pragma unroll
    for (int o = 16; o; o >>= 1) v = fmaxf(v, __shfl_xor_sync(0xffffffffu, v, o));
    return v;
}

__global__ void ln_rows(const float* __restrict__ base, const int* __restrict__ idx,
                        const float* __restrict__ g, float* __restrict__ dst,
                        long rowStride)
{
    int row = blockIdx.x;
    const float* src = base + (idx ? (size_t)idx[row] * rowStride
                                   : (size_t)row * rowStride);
    int tid = threadIdx.x, lane = tid & 31, w = tid >> 5;
    __shared__ float sb[8];
    float v0 = src[tid], v1 = src[tid + 256];
    float s = warpSum(v0 + v1);
    if (lane == 0) sb[w] = s;
    __syncthreads();
    float tot = 0.f;
#pragma unroll
    for (int i = 0; i < 8; i++) tot += sb[i];
    float m = tot * (1.f / 512.f);
    float a0 = v0 - m, a1 = v1 - m;
    __syncthreads();
    float q = warpSum(a0*a0 + a1*a1);
    if (lane == 0) sb[w] = q;
    __syncthreads();
    float var = 0.f;
#pragma unroll
    for (int i = 0; i < 8; i++) var += sb[i];
    var *= (1.f / 512.f);
    float inv = rsqrtf(var + 1e-5f);
    float* dr = dst + (size_t)row * 512;
    dr[tid]       = a0 * inv * g[tid];
    dr[tid + 256] = a1 * inv * g[tid + 256];
}

__global__ void softmax_rows(float* __restrict__ data, int ncol)
{
    float* row = data + (size_t)blockIdx.x * ncol;
    __shared__ float sb[8];
    int tid = threadIdx.x, lane = tid & 31, w = tid >> 5;
    float m = -INFINITY;
    for (int c = tid; c < ncol; c += 256) m = fmaxf(m, row[c]);
    m = warpMax(m);
    if (lane == 0) sb[w] = m;
    __syncthreads();
    float bm = sb[0];
#pragma unroll
    for (int i = 1; i < 8; i++) bm = fmaxf(bm, sb[i]);
    __syncthreads();
    float s = 0.f;
    for (int c = tid; c < ncol; c += 256) s += __expf(row[c] - bm);
    s = warpSum(s);
    if (lane == 0) sb[w] = s;
    __syncthreads();
    float bs = 0.f;
#pragma unroll
    for (int i = 0; i < 8; i++) bs += sb[i];
    float inv = 1.f / bs;
    for (int c = tid; c < ncol; c += 256) row[c] = __expf(row[c] - bm) * inv;
}

__global__ void col_mean_part(const float* __restrict__ wte)
{
    int d = blockIdx.x * 128 + threadIdx.x;
    int z = blockIdx.y;
    float s = 0.f;
    int v0 = z * 1000;
    for (int v = v0; v < v0 + 1000; v++) s += wte[(size_t)v * Dc + d];
    d_cmeanp[z * Dc + d] = s;
}
__global__ void col_mean_reduce()
{
    int d = blockIdx.x * 128 + threadIdx.x;
    float s = 0.f;
#pragma unroll
    for (int z = 0; z < 32; z++) s += d_cmeanp[z * Dc + d];
    d_cmean[d] = s * (1.f / 32000.f);
}

__global__ void vm_mean_k()
{
    int i = blockIdx.x * 256 + threadIdx.x;
    d_vm[i] = d_e[i] - d_cmean[i & (Dc - 1)];
}

__global__ void den_reduce()
{
    int r = blockIdx.x * 256 + threadIdx.x;
    float s = 0.f;
    for (int x = 0; x < Vc/128; x++) s += d_denp[(size_t)x * Rc + r];
    d_den[r] = s;
}

// vm = e - (sum_z part[z]) / den[row]
__global__ void vm_combine()
{
    int i = blockIdx.x * 256 + threadIdx.x;
    int r = i >> 9;
    float num = 0.f;
#pragma unroll
    for (int z = 0; z < NSPLIT; z++) num += d_part[(size_t)z * ((size_t)Rc*Dc) + i];
    d_vm[i] = d_e[i] - num / d_den[r];
}

__global__ void f2bf(const float* __restrict__ in, __nv_bfloat16* __restrict__ out)
{
    size_t i = (size_t)blockIdx.x * 256 + threadIdx.x;
    float2 v = ((const float2*)in)[i];
    ((__nv_bfloat162*)out)[i] = __float22bfloat162_rn(v);
}

__global__ void transpose_wte(const float* __restrict__ w, __nv_bfloat16* __restrict__ o)
{
    __shared__ float t[32][33];
    int v0 = blockIdx.x * 32, d0 = blockIdx.y * 32;
    int tx = threadIdx.x, ty = threadIdx.y;
    for (int i = ty; i < 32; i += 8) t[i][tx] = w[(size_t)(v0 + i) * Dc + d0 + tx];
    __syncthreads();
    for (int i = ty; i < 32; i += 8)
        o[(size_t)(d0 + i) * Vc + v0 + tx] = __float2bfloat16(t[tx][i]);
}

__global__ void logits_kernel(const float* __restrict__ last,
                              const float* __restrict__ wte,
                              float* __restrict__ out)
{
    int w = threadIdx.x >> 5, lane = threadIdx.x & 31;
    int v = blockIdx.x * 8 + w;
    int b = blockIdx.y;
    const float* q = last + b * 512;
    const float* wr = wte + (size_t)v * 512;
    float s = 0.f;
#pragma unroll
    for (int d = lane; d < 512; d += 32) s = fmaf(q[d], wr[d], s);
    s = warpSum(s);
    if (lane == 0) out[(size_t)b * Vc + v] = s;
}

// ---------------- launch ----------------
extern "C" void kernel_launch(void* const* d_in, const int* in_sizes, int n_in,
                              void* d_out, int out_size)
{
    const int*   x   = (const int*)  d_in[0];
    const float* wte = (const float*)d_in[1];
    const float* wpe = (const float*)d_in[2];
    const float* g_e = (const float*)d_in[3];
    const float* g_p = (const float*)d_in[4];
    const float* g_f = (const float*)d_in[5];
    const float* W_q = (const float*)d_in[6];
    const float* W_k = (const float*)d_in[7];
    const float* W_o = (const float*)d_in[8];
    float* out = (float*)d_out;

    float *e, *p, *Q, *Kt, *krn, *fk, *vm, *delta, *part, *last, *denp;
    __nv_bfloat16 *E, *wte_bf, *wteT_bf, *fk_bf;
    cudaGetSymbolAddress((void**)&e,     d_e);
    cudaGetSymbolAddress((void**)&p,     d_p);
    cudaGetSymbolAddress((void**)&Q,     d_Q);
    cudaGetSymbolAddress((void**)&Kt,    d_Kt);
    cudaGetSymbolAddress((void**)&krn,   d_krn);
    cudaGetSymbolAddress((void**)&fk,    d_fk);
    cudaGetSymbolAddress((void**)&vm,    d_vm);
    cudaGetSymbolAddress((void**)&delta, d_delta);
    cudaGetSymbolAddress((void**)&part,  d_part);
    cudaGetSymbolAddress((void**)&last,  d_last);
    cudaGetSymbolAddress((void**)&denp,  d_denp);
    cudaGetSymbolAddress((void**)&E,       d_E);
    cudaGetSymbolAddress((void**)&wte_bf,  d_wte_bf);
    cudaGetSymbolAddress((void**)&wteT_bf, d_wteT_bf);
    cudaGetSymbolAddress((void**)&fk_bf,   d_fk_bf);

    const long SD = (long)Sc * Dc;
    const long SS = (long)Sc * Sc;
    const float attnScale = 0.044194173824159216f;  // 1/sqrt(512)

    // embeddings + positional LN
    ln_rows<<<Rc,   256>>>(wte, x, g_e, e, (long)Dc);
    ln_rows<<<Sc+1, 256>>>(wpe, nullptr, g_p, p, (long)Dc);

    // layer-0 ex_wte = column mean of wte
    col_mean_part<<<dim3(4, 32), 128>>>(wte);
    col_mean_reduce<<<4, 128>>>();

    // bf16 copies of wte (once)
    f2bf<<<(Vc*Dc/2)/256, 256>>>(wte, wte_bf);
    transpose_wte<<<dim3(Vc/32, Dc/32), dim3(32, 8)>>>(wte, wteT_bf);

    // Q/K/krn (fp32)
    sgemm_nn<<<dim3(4,4,4),256>>>(Sc,Dc,Dc, p+Dc,Dc, W_q,Dc, Q,Dc,
                                  0, EPI_NONE, 0.f, 1,
                                  0,0, 0,(long)Dc*Dc, 0,SD);
    sgemm_nn<<<dim3(4,4,4),256>>>(Sc,Dc,Dc, p,Dc, W_k,Dc, Kt,Dc,
                                  0, EPI_NONE, 0.f, 1,
                                  0,0, 0,(long)Dc*Dc, 0,SD);
    sgemm_nt<<<dim3(4,4,4),256>>>(Sc,Sc,Dc, Q,Dc, Kt,Dc, krn,Sc,
                                  0, EPI_ATTN, attnScale, 1,
                                  0,SD, 0,SD, 0,SS);
    softmax_rows<<<Hc*Sc, 256>>>(krn, Sc);

    cudaMemsetAsync(fk, 0, (size_t)Rc * Dc * sizeof(float), 0);

    for (int layer = 0; layer < 4; layer++) {
        if (layer == 0) {
            vm_mean_k<<<Rc*Dc/256, 256>>>();
        } else {
            // E = exp(f_k @ wte^T) via bf16 HMMA, fused row-sum partials
            f2bf<<<(Rc*Dc/2)/256, 256>>>(fk, fk_bf);
            mma_vocab<0><<<dim3(Vc/128, Rc/128, 1), 256>>>(
                fk_bf, (long)Dc, wte_bf, (long)Dc, Dc/32, E, denp, nullptr);
            den_reduce<<<Rc/256, 256>>>();
            // num = E @ wte (as E @ wteT^T), split-K over 10 chunks
            mma_vocab<1><<<dim3(Dc/128, Rc/128, NSPLIT), 256>>>(
                E, (long)Vc, wteT_bf, (long)Vc, (Vc/NSPLIT)/32, nullptr, nullptr, part);
            vm_combine<<<Rc*Dc/256, 256>>>();
        }
        // delta[b,:,h,:] = coef * (krn[h] @ Vm[b])  (fp32, batched z = b*4+h)
        sgemm_nn<<<dim3(4,4,16),256>>>(Sc,Dc,Sc, krn,Sc, vm,Dc, delta,HDc,
                                       0, EPI_COEF, 0.f, 4,
                                       SS, 0,
                                       0, SD,
                                       (long)Dc, (long)Sc*HDc);
        // f_k += delta_flat @ W_o^T (fp32)
        sgemm_nt<<<dim3(Dc/128, Rc/128, 1),256>>>(Rc,Dc,HDc, delta,HDc, W_o,HDc, fk,Dc,
                                                  1, EPI_NONE, 0.f, 1,
                                                  0,0,0,0,0,0);
    }

    ln_rows<<<Bc, 256>>>(fk + (size_t)(Sc-1)*Dc, nullptr, g_f, last, (long)Sc*Dc);
    logits_kernel<<<dim3(Vc/8, Bc), 256>>>(last, wte, out);
}

// round 4
// speedup vs baseline: 3.5016x; 1.0271x over previous
#include <cuda_runtime.h>
#include <cuda_bf16.h>
#include <math.h>
#include <stdint.h>

// Problem constants
#define Bc 4
#define Sc 512
#define Dc 512
#define Hc 4
#define Vc 32000
#define Rc (Bc*Sc)    // 2048 query rows
#define HDc (Hc*Dc)   // 2048
#define NSPLIT 10

// ---------------- scratch (device globals: allocation-free) ----------------
__device__ float d_e[Rc*Dc];                     // LN(wte[x])
__device__ float d_p[(Sc+1)*Dc];                 // LN(wpe)
__device__ float d_Q[Hc*Sc*Dc];
__device__ float d_Kt[Hc*Sc*Dc];
__device__ float d_krn[Hc*Sc*Sc];
__device__ float d_fk[Rc*Dc];
__device__ float d_vm[Rc*Dc];
__device__ float d_delta[Rc*HDc];
__device__ float d_part[(size_t)NSPLIT*Rc*Dc];   // split-K fp32 partials (num)
__device__ float d_cmeanp[32*Dc];
__device__ float d_cmean[Dc];
__device__ float d_last[Bc*Dc];
// bf16 path
__device__ __nv_bfloat16 d_E[(size_t)Rc*Vc];         // exp(scores), bf16 (131MB)
__device__ __nv_bfloat16 d_wte_bf[(size_t)Vc*Dc];    // wte bf16 [v,d]
__device__ __nv_bfloat16 d_wteT_bf[(size_t)Dc*Vc];   // wte bf16 transposed [d,v]
__device__ __nv_bfloat16 d_fk_bf[Rc*Dc];
__device__ float d_denp[(Vc/128)*Rc];                // per-x-block row sums of E
__device__ float d_den[Rc];

// =================== PTX helpers ===================
__device__ __forceinline__ uint32_t smem_u32(const void* p){
    uint32_t a;
    asm("{ .reg .u64 t; cvta.to.shared.u64 t, %1; cvt.u32.u64 %0, t; }":"=r"(a):"l"(p));
    return a;
}
__device__ __forceinline__ void cp16(uint32_t s, const void* g){
    asm volatile("cp.async.cg.shared.global [%0], [%1], 16;"::"r"(s),"l"(g));
}
__device__ __forceinline__ void cp_commit(){ asm volatile("cp.async.commit_group;"); }
template<int N> __device__ __forceinline__ void cp_wait(){ asm volatile("cp.async.wait_group %0;"::"n"(N)); }

__device__ __forceinline__ void ldm_x4(uint32_t& r0,uint32_t& r1,uint32_t& r2,uint32_t& r3,uint32_t addr){
    asm volatile("ldmatrix.sync.aligned.m8n8.x4.shared.b16 {%0,%1,%2,%3}, [%4];"
      : "=r"(r0),"=r"(r1),"=r"(r2),"=r"(r3) : "r"(addr));
}
__device__ __forceinline__ void mma16816(float* c, uint32_t a0,uint32_t a1,uint32_t a2,uint32_t a3,
                                         uint32_t b0,uint32_t b1){
    asm volatile("mma.sync.aligned.m16n8k16.row.col.f32.bf16.bf16.f32 "
      "{%0,%1,%2,%3}, {%4,%5,%6,%7}, {%8,%9}, {%0,%1,%2,%3};"
      : "+f"(c[0]),"+f"(c[1]),"+f"(c[2]),"+f"(c[3])
      : "r"(a0),"r"(a1),"r"(a2),"r"(a3),"r"(b0),"r"(b1));
}

// =================== bf16 HMMA vocab GEMM ===================
// C[128,128] per CTA = A(128 x K) @ B(128 x K)^T, both K-major bf16.
// MODE 0: C -> exp(min(C,70)): bf16 Eout (row stride Vc) + row-sum partials denPart.
// MODE 1: C -> fp32 partial buffer z (row stride Dc), split-K over blockIdx.z.
#define PITCH 80           // 32 bf16 data + 8 pad, conflict-free for ldmatrix
#define ABUF  10240        // 128 * 80
#define TBUF  20480        // A + B per stage

template<int MODE>
__global__ void __launch_bounds__(256)
mma_vocab(const __nv_bfloat16* __restrict__ A, long lda,
          const __nv_bfloat16* __restrict__ B, long ldb,
          int kTiles,
          __nv_bfloat16* __restrict__ Eout, float* __restrict__ denPart,
          float* __restrict__ Pout)
{
    __shared__ char smem[2*TBUF];                 // 40 KB double-buffered
    const uint32_t sb = smem_u32(smem);
    const int tid = threadIdx.x, lane = tid & 31, wid = tid >> 5;
    const int wm = wid & 1, wn = wid >> 1;        // 2 x 4 warp grid
    const int wmBase = wm * 64, wnBase = wn * 32;
    const int rowBase = blockIdx.y << 7, colBase = blockIdx.x << 7;
    const long k0base = (long)blockIdx.z * kTiles * 32;

    float acc[4][4][4];
#pragma unroll
    for (int mt = 0; mt < 4; mt++)
#pragma unroll
        for (int nt = 0; nt < 4; nt++)
#pragma unroll
            for (int q = 0; q < 4; q++) acc[mt][nt][q] = 0.f;

    // ldmatrix lane address components
    const int ar = lane & 15;                     // A row within 16
    const int akof = (lane >> 4) * 8;             // A k offset 0/8
    const int bn = (lane & 7) + ((lane & 16) ? 8 : 0);   // B n within 16
    const int bkof = ((lane >> 3) & 1) * 8;       // B k offset 0/8

    // tile loader: 128 rows x 64B each for A and B
    auto load = [&](int buf, long k0){
        uint32_t base = sb + buf*TBUF;
#pragma unroll
        for (int i = 0; i < 2; i++){
            int c = tid + i*256; int r = c >> 2, s = c & 3;
            cp16(base + r*PITCH + s*16, A + (size_t)(rowBase + r)*lda + k0 + s*8);
        }
#pragma unroll
        for (int i = 0; i < 2; i++){
            int c = tid + i*256; int r = c >> 2, s = c & 3;
            cp16(base + ABUF + r*PITCH + s*16, B + (size_t)(colBase + r)*ldb + k0 + s*8);
        }
        cp_commit();
    };

    load(0, k0base);
    for (int t = 0; t < kTiles; t++){
        if (t + 1 < kTiles){ load((t+1)&1, k0base + (long)(t+1)*32); cp_wait<1>(); }
        else cp_wait<0>();
        __syncthreads();
        uint32_t base = sb + (t&1)*TBUF;
#pragma unroll
        for (int kk = 0; kk < 2; kk++){
            uint32_t a[4][4], b[2][4];
            uint32_t aCol = (uint32_t)((kk*16 + akof) * 2);
            uint32_t bCol = (uint32_t)((kk*16 + bkof) * 2);
#pragma unroll
            for (int mt = 0; mt < 4; mt++)
                ldm_x4(a[mt][0], a[mt][1], a[mt][2], a[mt][3],
                       base + (uint32_t)(wmBase + mt*16 + ar)*PITCH + aCol);
#pragma unroll
            for (int j = 0; j < 2; j++)
                ldm_x4(b[j][0], b[j][1], b[j][2], b[j][3],
                       base + ABUF + (uint32_t)(wnBase + j*16 + bn)*PITCH + bCol);
#pragma unroll
            for (int mt = 0; mt < 4; mt++)
#pragma unroll
                for (int nt = 0; nt < 4; nt++)
                    mma16816(acc[mt][nt], a[mt][0], a[mt][1], a[mt][2], a[mt][3],
                             b[nt>>1][(nt&1)*2], b[nt>>1][(nt&1)*2 + 1]);
        }
        __syncthreads();
    }

    // epilogue: thread owns rows r0 = wmBase+mt*16+lane/4, r1 = r0+8,
    // cols wnBase + nt*8 + (lane&3)*2 (+1)
    if (MODE == 0){
        float* denm = (float*)smem;               // [128][4] cross-warp reduce
        int cq = (lane & 3) * 2;
#pragma unroll
        for (int mt = 0; mt < 4; mt++){
            int lr0 = wmBase + mt*16 + (lane >> 2);
            int r0 = rowBase + lr0;
            float s0 = 0.f, s1 = 0.f;
#pragma unroll
            for (int nt = 0; nt < 4; nt++){
                int col = colBase + wnBase + nt*8 + cq;
                float e0 = __expf(fminf(acc[mt][nt][0], 70.f));
                float e1 = __expf(fminf(acc[mt][nt][1], 70.f));
                float e2 = __expf(fminf(acc[mt][nt][2], 70.f));
                float e3 = __expf(fminf(acc[mt][nt][3], 70.f));
                s0 += e0 + e1; s1 += e2 + e3;
                __nv_bfloat162 p0 = __float22bfloat162_rn(make_float2(e0, e1));
                __nv_bfloat162 p1 = __float22bfloat162_rn(make_float2(e2, e3));
                *(__nv_bfloat162*)(Eout + (size_t)r0*Vc + col) = p0;
                *(__nv_bfloat162*)(Eout + (size_t)(r0+8)*Vc + col) = p1;
            }
            s0 += __shfl_xor_sync(0xffffffffu, s0, 1);
            s0 += __shfl_xor_sync(0xffffffffu, s0, 2);
            s1 += __shfl_xor_sync(0xffffffffu, s1, 1);
            s1 += __shfl_xor_sync(0xffffffffu, s1, 2);
            if ((lane & 3) == 0){
                denm[lr0*4 + wn] = s0;
                denm[(lr0+8)*4 + wn] = s1;
            }
        }
        __syncthreads();
        if (tid < 128){
            float d = denm[tid*4] + denm[tid*4+1] + denm[tid*4+2] + denm[tid*4+3];
            denPart[(size_t)blockIdx.x * Rc + rowBase + tid] = d;
        }
    } else {
        float* dst = Pout + (size_t)blockIdx.z * ((size_t)Rc*Dc);
        int cq = (lane & 3) * 2;
#pragma unroll
        for (int mt = 0; mt < 4; mt++){
            int r0 = rowBase + wmBase + mt*16 + (lane >> 2);
#pragma unroll
            for (int nt = 0; nt < 4; nt++){
                int col = colBase + wnBase + nt*8 + cq;
                *(float2*)(dst + (size_t)r0*Dc + col) =
                    make_float2(acc[mt][nt][0], acc[mt][nt][1]);
                *(float2*)(dst + (size_t)(r0+8)*Dc + col) =
                    make_float2(acc[mt][nt][2], acc[mt][nt][3]);
            }
        }
    }
}

// =================== fp32 SGEMM (small GEMMs) ===================
#define EPI_NONE 0
#define EPI_ATTN 1
#define EPI_COEF 2
#define BM 128
#define BN 128
#define BK 8

__global__ void __launch_bounds__(256)
sgemm_nn(int M, int N, int K,
         const float* __restrict__ A, int lda,
         const float* __restrict__ B, int ldb,
         float* __restrict__ C, int ldc,
         int beta, int epi, float scale,
         int zdiv,
         long sAlo, long sAhi, long sBlo, long sBhi, long sClo, long sChi)
{
    __shared__ float As[BK][BM];
    __shared__ float Bs[BK][BN];
    int z = blockIdx.z;
    {
        int lo = z % zdiv, hi = z / zdiv;
        A += (size_t)lo * sAlo + (size_t)hi * sAhi;
        B += (size_t)lo * sBlo + (size_t)hi * sBhi;
        C += (size_t)lo * sClo + (size_t)hi * sChi;
    }
    const int tid = threadIdx.x;
    const int tx = tid & 15, ty = tid >> 4;
    const int rowBase = blockIdx.y * BM, colBase = blockIdx.x * BN;
    const int aRow = tid >> 1,  aCol = (tid & 1) << 2;
    const int bRow = tid >> 5,  bCol = (tid & 31) << 2;

    float acc[8][8];
#pragma unroll
    for (int i = 0; i < 8; i++)
#pragma unroll
        for (int j = 0; j < 8; j++) acc[i][j] = 0.f;

    for (int k0 = 0; k0 < K; k0 += BK) {
        float4 av = *(const float4*)(A + (size_t)(rowBase + aRow) * lda + k0 + aCol);
        As[aCol+0][aRow] = av.x; As[aCol+1][aRow] = av.y;
        As[aCol+2][aRow] = av.z; As[aCol+3][aRow] = av.w;
        float4 bv = *(const float4*)(B + (size_t)(k0 + bRow) * ldb + colBase + bCol);
        *(float4*)&Bs[bRow][bCol] = bv;
        __syncthreads();
#pragma unroll
        for (int kk = 0; kk < BK; kk++) {
            float a[8], b[8];
            *(float4*)&a[0] = *(const float4*)&As[kk][ty*8];
            *(float4*)&a[4] = *(const float4*)&As[kk][ty*8+4];
            *(float4*)&b[0] = *(const float4*)&Bs[kk][tx*8];
            *(float4*)&b[4] = *(const float4*)&Bs[kk][tx*8+4];
#pragma unroll
            for (int i = 0; i < 8; i++)
#pragma unroll
                for (int j = 0; j < 8; j++) acc[i][j] = fmaf(a[i], b[j], acc[i][j]);
        }
        __syncthreads();
    }
#pragma unroll
    for (int i = 0; i < 8; i++) {
        int r = rowBase + ty*8 + i;
#pragma unroll
        for (int j = 0; j < 8; j++) {
            int c = colBase + tx*8 + j;
            float v = acc[i][j];
            if (epi == EPI_ATTN) {
                v *= scale;
                v = fminf(10.f, fmaxf(-10.f, v));
                if (c > r) v = -INFINITY;
            } else if (epi == EPI_COEF) {
                v *= 1.0f / (1.0f + (float)r);
            }
            size_t ci = (size_t)r * ldc + c;
            if (beta) C[ci] += v; else C[ci] = v;
        }
    }
}

__global__ void __launch_bounds__(256)
sgemm_nt(int M, int N, int K,
         const float* __restrict__ A, int lda,
         const float* __restrict__ B, int ldb,
         float* __restrict__ C, int ldc,
         int beta, int epi, float scale,
         int zdiv,
         long sAlo, long sAhi, long sBlo, long sBhi, long sClo, long sChi)
{
    __shared__ float As[BK][BM];
    __shared__ float Bs[BK][BN];
    int z = blockIdx.z;
    {
        int lo = z % zdiv, hi = z / zdiv;
        A += (size_t)lo * sAlo + (size_t)hi * sAhi;
        B += (size_t)lo * sBlo + (size_t)hi * sBhi;
        C += (size_t)lo * sClo + (size_t)hi * sChi;
    }
    const int tid = threadIdx.x;
    const int tx = tid & 15, ty = tid >> 4;
    const int rowBase = blockIdx.y * BM, colBase = blockIdx.x * BN;
    const int aRow = tid >> 1, aCol = (tid & 1) << 2;
    const int bN   = tid >> 1, bK   = (tid & 1) << 2;

    float acc[8][8];
#pragma unroll
    for (int i = 0; i < 8; i++)
#pragma unroll
        for (int j = 0; j < 8; j++) acc[i][j] = 0.f;

    for (int k0 = 0; k0 < K; k0 += BK) {
        float4 av = *(const float4*)(A + (size_t)(rowBase + aRow) * lda + k0 + aCol);
        As[aCol+0][aRow] = av.x; As[aCol+1][aRow] = av.y;
        As[aCol+2][aRow] = av.z; As[aCol+3][aRow] = av.w;
        float4 bv = *(const float4*)(B + (size_t)(colBase + bN) * ldb + k0 + bK);
        Bs[bK+0][bN] = bv.x; Bs[bK+1][bN] = bv.y;
        Bs[bK+2][bN] = bv.z; Bs[bK+3][bN] = bv.w;
        __syncthreads();
#pragma unroll
        for (int kk = 0; kk < BK; kk++) {
            float a[8], b[8];
            *(float4*)&a[0] = *(const float4*)&As[kk][ty*8];
            *(float4*)&a[4] = *(const float4*)&As[kk][ty*8+4];
            *(float4*)&b[0] = *(const float4*)&Bs[kk][tx*8];
            *(float4*)&b[4] = *(const float4*)&Bs[kk][tx*8+4];
#pragma unroll
            for (int i = 0; i < 8; i++)
#pragma unroll
                for (int j = 0; j < 8; j++) acc[i][j] = fmaf(a[i], b[j], acc[i][j]);
        }
        __syncthreads();
    }
#pragma unroll
    for (int i = 0; i < 8; i++) {
        int r = rowBase + ty*8 + i;
#pragma unroll
        for (int j = 0; j < 8; j++) {
            int c = colBase + tx*8 + j;
            float v = acc[i][j];
            if (epi == EPI_ATTN) {
                v *= scale;
                v = fminf(10.f, fmaxf(-10.f, v));
                if (c > r) v = -INFINITY;
            } else if (epi == EPI_COEF) {
                v *= 1.0f / (1.0f + (float)r);
            }
            size_t ci = (size_t)r * ldc + c;
            if (beta) C[ci] += v; else C[ci] = v;
        }
    }
}

// ---------------- reductions / elementwise ----------------
__device__ __forceinline__ float warpSum(float v) {
#pragma unroll
    for (int o = 16; o; o >>= 1) v += __shfl_xor_sync(0xffffffffu, v, o);
    return v;
}
__device__ __forceinline__ float warpMax(float v) {
#pragma unroll
    for (int o = 16; o; o >>= 1) v = fmaxf(v, __shfl_xor_sync(0xffffffffu, v, o));
    return v;
}

__global__ void ln_rows(const float* __restrict__ base, const int* __restrict__ idx,
                        const float* __restrict__ g, float* __restrict__ dst,
                        long rowStride)
{
    int row = blockIdx.x;
    const float* src = base + (idx ? (size_t)idx[row] * rowStride
                                   : (size_t)row * rowStride);
    int tid = threadIdx.x, lane = tid & 31, w = tid >> 5;
    __shared__ float sb[8];
    float v0 = src[tid], v1 = src[tid + 256];
    float s = warpSum(v0 + v1);
    if (lane == 0) sb[w] = s;
    __syncthreads();
    float tot = 0.f;
#pragma unroll
    for (int i = 0; i < 8; i++) tot += sb[i];
    float m = tot * (1.f / 512.f);
    float a0 = v0 - m, a1 = v1 - m;
    __syncthreads();
    float q = warpSum(a0*a0 + a1*a1);
    if (lane == 0) sb[w] = q;
    __syncthreads();
    float var = 0.f;
#pragma unroll
    for (int i = 0; i < 8; i++) var += sb[i];
    var *= (1.f / 512.f);
    float inv = rsqrtf(var + 1e-5f);
    float* dr = dst + (size_t)row * 512;
    dr[tid]       = a0 * inv * g[tid];
    dr[tid + 256] = a1 * inv * g[tid + 256];
}

__global__ void softmax_rows(float* __restrict__ data, int ncol)
{
    float* row = data + (size_t)blockIdx.x * ncol;
    __shared__ float sb[8];
    int tid = threadIdx.x, lane = tid & 31, w = tid >> 5;
    float m = -INFINITY;
    for (int c = tid; c < ncol; c += 256) m = fmaxf(m, row[c]);
    m = warpMax(m);
    if (lane == 0) sb[w] = m;
    __syncthreads();
    float bm = sb[0];
#pragma unroll
    for (int i = 1; i < 8; i++) bm = fmaxf(bm, sb[i]);
    __syncthreads();
    float s = 0.f;
    for (int c = tid; c < ncol; c += 256) s += __expf(row[c] - bm);
    s = warpSum(s);
    if (lane == 0) sb[w] = s;
    __syncthreads();
    float bs = 0.f;
#pragma unroll
    for (int i = 0; i < 8; i++) bs += sb[i];
    float inv = 1.f / bs;
    for (int c = tid; c < ncol; c += 256) row[c] = __expf(row[c] - bm) * inv;
}

__global__ void col_mean_part(const float* __restrict__ wte)
{
    int d = blockIdx.x * 128 + threadIdx.x;
    int z = blockIdx.y;
    float s = 0.f;
    int v0 = z * 1000;
    for (int v = v0; v < v0 + 1000; v++) s += wte[(size_t)v * Dc + d];
    d_cmeanp[z * Dc + d] = s;
}
__global__ void col_mean_reduce()
{
    int d = blockIdx.x * 128 + threadIdx.x;
    float s = 0.f;
#pragma unroll
    for (int z = 0; z < 32; z++) s += d_cmeanp[z * Dc + d];
    d_cmean[d] = s * (1.f / 32000.f);
}

__global__ void vm_mean_k()
{
    int i = blockIdx.x * 256 + threadIdx.x;
    d_vm[i] = d_e[i] - d_cmean[i & (Dc - 1)];
}

__global__ void den_reduce()
{
    int r = blockIdx.x * 256 + threadIdx.x;
    float s = 0.f;
    for (int x = 0; x < Vc/128; x++) s += d_denp[(size_t)x * Rc + r];
    d_den[r] = s;
}

// vm = e - (sum_z part[z]) / den[row]
__global__ void vm_combine()
{
    int i = blockIdx.x * 256 + threadIdx.x;
    int r = i >> 9;
    float num = 0.f;
#pragma unroll
    for (int z = 0; z < NSPLIT; z++) num += d_part[(size_t)z * ((size_t)Rc*Dc) + i];
    d_vm[i] = d_e[i] - num / d_den[r];
}

__global__ void f2bf(const float* __restrict__ in, __nv_bfloat16* __restrict__ out)
{
    size_t i = (size_t)blockIdx.x * 256 + threadIdx.x;
    float2 v = ((const float2*)in)[i];
    ((__nv_bfloat162*)out)[i] = __float22bfloat162_rn(v);
}

__global__ void transpose_wte(const float* __restrict__ w, __nv_bfloat16* __restrict__ o)
{
    __shared__ float t[32][33];
    int v0 = blockIdx.x * 32, d0 = blockIdx.y * 32;
    int tx = threadIdx.x, ty = threadIdx.y;
    for (int i = ty; i < 32; i += 8) t[i][tx] = w[(size_t)(v0 + i) * Dc + d0 + tx];
    __syncthreads();
    for (int i = ty; i < 32; i += 8)
        o[(size_t)(d0 + i) * Vc + v0 + tx] = __float2bfloat16(t[tx][i]);
}

__global__ void logits_kernel(const float* __restrict__ last,
                              const float* __restrict__ wte,
                              float* __restrict__ out)
{
    int w = threadIdx.x >> 5, lane = threadIdx.x & 31;
    int v = blockIdx.x * 8 + w;
    int b = blockIdx.y;
    const float* q = last + b * 512;
    const float* wr = wte + (size_t)v * 512;
    float s = 0.f;
#pragma unroll
    for (int d = lane; d < 512; d += 32) s = fmaf(q[d], wr[d], s);
    s = warpSum(s);
    if (lane == 0) out[(size_t)b * Vc + v] = s;
}

// ---------------- launch ----------------
extern "C" void kernel_launch(void* const* d_in, const int* in_sizes, int n_in,
                              void* d_out, int out_size)
{
    const int*   x   = (const int*)  d_in[0];
    const float* wte = (const float*)d_in[1];
    const float* wpe = (const float*)d_in[2];
    const float* g_e = (const float*)d_in[3];
    const float* g_p = (const float*)d_in[4];
    const float* g_f = (const float*)d_in[5];
    const float* W_q = (const float*)d_in[6];
    const float* W_k = (const float*)d_in[7];
    const float* W_o = (const float*)d_in[8];
    float* out = (float*)d_out;

    float *e, *p, *Q, *Kt, *krn, *fk, *vm, *delta, *part, *last, *denp;
    __nv_bfloat16 *E, *wte_bf, *wteT_bf, *fk_bf;
    cudaGetSymbolAddress((void**)&e,     d_e);
    cudaGetSymbolAddress((void**)&p,     d_p);
    cudaGetSymbolAddress((void**)&Q,     d_Q);
    cudaGetSymbolAddress((void**)&Kt,    d_Kt);
    cudaGetSymbolAddress((void**)&krn,   d_krn);
    cudaGetSymbolAddress((void**)&fk,    d_fk);
    cudaGetSymbolAddress((void**)&vm,    d_vm);
    cudaGetSymbolAddress((void**)&delta, d_delta);
    cudaGetSymbolAddress((void**)&part,  d_part);
    cudaGetSymbolAddress((void**)&last,  d_last);
    cudaGetSymbolAddress((void**)&denp,  d_denp);
    cudaGetSymbolAddress((void**)&E,       d_E);
    cudaGetSymbolAddress((void**)&wte_bf,  d_wte_bf);
    cudaGetSymbolAddress((void**)&wteT_bf, d_wteT_bf);
    cudaGetSymbolAddress((void**)&fk_bf,   d_fk_bf);

    const long SD = (long)Sc * Dc;
    const long SS = (long)Sc * Sc;
    const float attnScale = 0.044194173824159216f;  // 1/sqrt(512)

    // embeddings + positional LN
    ln_rows<<<Rc,   256>>>(wte, x, g_e, e, (long)Dc);
    ln_rows<<<Sc+1, 256>>>(wpe, nullptr, g_p, p, (long)Dc);

    // layer-0 ex_wte = column mean of wte
    col_mean_part<<<dim3(4, 32), 128>>>(wte);
    col_mean_reduce<<<4, 128>>>();

    // bf16 copies of wte (once)
    f2bf<<<(Vc*Dc/2)/256, 256>>>(wte, wte_bf);
    transpose_wte<<<dim3(Vc/32, Dc/32), dim3(32, 8)>>>(wte, wteT_bf);

    // Q/K/krn (fp32)
    sgemm_nn<<<dim3(4,4,4),256>>>(Sc,Dc,Dc, p+Dc,Dc, W_q,Dc, Q,Dc,
                                  0, EPI_NONE, 0.f, 1,
                                  0,0, 0,(long)Dc*Dc, 0,SD);
    sgemm_nn<<<dim3(4,4,4),256>>>(Sc,Dc,Dc, p,Dc, W_k,Dc, Kt,Dc,
                                  0, EPI_NONE, 0.f, 1,
                                  0,0, 0,(long)Dc*Dc, 0,SD);
    sgemm_nt<<<dim3(4,4,4),256>>>(Sc,Sc,Dc, Q,Dc, Kt,Dc, krn,Sc,
                                  0, EPI_ATTN, attnScale, 1,
                                  0,SD, 0,SD, 0,SS);
    softmax_rows<<<Hc*Sc, 256>>>(krn, Sc);

    cudaMemsetAsync(fk, 0, (size_t)Rc * Dc * sizeof(float), 0);

    for (int layer = 0; layer < 4; layer++) {
        if (layer == 0) {
            vm_mean_k<<<Rc*Dc/256, 256>>>();
        } else {
            // E = exp(f_k @ wte^T) via bf16 HMMA, fused row-sum partials
            f2bf<<<(Rc*Dc/2)/256, 256>>>(fk, fk_bf);
            mma_vocab<0><<<dim3(Vc/128, Rc/128, 1), 256>>>(
                fk_bf, (long)Dc, wte_bf, (long)Dc, Dc/32, E, denp, nullptr);
            den_reduce<<<Rc/256, 256>>>();
            // num = E @ wte (as E @ wteT^T), split-K over 10 chunks
            mma_vocab<1><<<dim3(Dc/128, Rc/128, NSPLIT), 256>>>(
                E, (long)Vc, wteT_bf, (long)Vc, (Vc/NSPLIT)/32, nullptr, nullptr, part);
            vm_combine<<<Rc*Dc/256, 256>>>();
        }
        // delta[b,:,h,:] = coef * (krn[h] @ Vm[b])  (fp32, batched z = b*4+h)
        sgemm_nn<<<dim3(4,4,16),256>>>(Sc,Dc,Sc, krn,Sc, vm,Dc, delta,HDc,
                                       0, EPI_COEF, 0.f, 4,
                                       SS, 0,
                                       0, SD,
                                       (long)Dc, (long)Sc*HDc);
        // f_k += delta_flat @ W_o^T (fp32)
        sgemm_nt<<<dim3(Dc/128, Rc/128, 1),256>>>(Rc,Dc,HDc, delta,HDc, W_o,HDc, fk,Dc,
                                                  1, EPI_NONE, 0.f, 1,
                                                  0,0,0,0,0,0);
    }

    ln_rows<<<Bc, 256>>>(fk + (size_t)(Sc-1)*Dc, nullptr, g_f, last, (long)Sc*Dc);
    logits_kernel<<<dim3(Vc/8, Bc), 256>>>(last, wte, out);
}

// round 5
// speedup vs baseline: 5.3821x; 1.5371x over previous
#include <cuda_runtime.h>
#include <cuda_bf16.h>
#include <math.h>
#include <stdint.h>

// Problem constants
#define Bc 4
#define Sc 512
#define Dc 512
#define Hc 4
#define Vc 32000
#define Rc (Bc*Sc)    // 2048 query rows
#define HDc (Hc*Dc)   // 2048
#define NSPLIT 10
#define K3 1536       // 3*512 split-K for delta
#define K6 6144       // 3*2048 split-K for W_o

// ---------------- scratch (device globals) ----------------
__device__ float d_e[Rc*Dc];
__device__ float d_p[(Sc+1)*Dc];
__device__ float d_Q[Hc*Sc*Dc];
__device__ float d_Kt[Hc*Sc*Dc];
__device__ float d_krn[Hc*Sc*Sc];
__device__ float d_fk[Rc*Dc];
__device__ float d_vm[Rc*Dc];
__device__ float d_delta[Rc*HDc];
__device__ float d_part[(size_t)NSPLIT*Rc*Dc];
__device__ float d_cmeanp[32*Dc];
__device__ float d_cmean[Dc];
__device__ float d_last[Bc*Dc];
__device__ __nv_bfloat16 d_E[(size_t)Rc*Vc];
__device__ __nv_bfloat16 d_wte_bf[(size_t)Vc*Dc];
__device__ __nv_bfloat16 d_wteT_bf[(size_t)Dc*Vc];
__device__ __nv_bfloat16 d_fk_bf[Rc*Dc];
__device__ float d_denp[(Vc/128)*Rc];
__device__ float d_den[Rc];
// split-bf16 buffers
__device__ __nv_bfloat16 d_krn3[(size_t)Hc*Sc*K3];     // [h][s][1536]
__device__ __nv_bfloat16 d_vm3t[(size_t)Bc*Dc*K3];     // [b][d][1536]
__device__ __nv_bfloat16 d_delta3[(size_t)Rc*K6];      // [r][6144]
__device__ __nv_bfloat16 d_wo3t[(size_t)Dc*K6];        // [n][6144]

// =================== PTX helpers ===================
__device__ __forceinline__ uint32_t smem_u32(const void* p){
    uint32_t a;
    asm("{ .reg .u64 t; cvta.to.shared.u64 t, %1; cvt.u32.u64 %0, t; }":"=r"(a):"l"(p));
    return a;
}
__device__ __forceinline__ void cp16(uint32_t s, const void* g){
    asm volatile("cp.async.cg.shared.global [%0], [%1], 16;"::"r"(s),"l"(g));
}
__device__ __forceinline__ void cp_commit(){ asm volatile("cp.async.commit_group;"); }
template<int N> __device__ __forceinline__ void cp_wait(){ asm volatile("cp.async.wait_group %0;"::"n"(N)); }

__device__ __forceinline__ void ldm_x4(uint32_t& r0,uint32_t& r1,uint32_t& r2,uint32_t& r3,uint32_t addr){
    asm volatile("ldmatrix.sync.aligned.m8n8.x4.shared.b16 {%0,%1,%2,%3}, [%4];"
      : "=r"(r0),"=r"(r1),"=r"(r2),"=r"(r3) : "r"(addr));
}
__device__ __forceinline__ void mma16816(float* c, uint32_t a0,uint32_t a1,uint32_t a2,uint32_t a3,
                                         uint32_t b0,uint32_t b1){
    asm volatile("mma.sync.aligned.m16n8k16.row.col.f32.bf16.bf16.f32 "
      "{%0,%1,%2,%3}, {%4,%5,%6,%7}, {%8,%9}, {%0,%1,%2,%3};"
      : "+f"(c[0]),"+f"(c[1]),"+f"(c[2]),"+f"(c[3])
      : "r"(a0),"r"(a1),"r"(a2),"r"(a3),"r"(b0),"r"(b1));
}

// =================== bf16 HMMA GEMM core ===================
// C[128,128] per CTA = A(128 x K) @ B(128 x K)^T, both K-major bf16.
// MODE 0: exp epilogue -> bf16 Eout (ld Vc) + row-sum partials denPart.
// MODE 1: fp32 -> Cout + z*(Rc*Dc), split-K chunk z (k0 = z*kTiles*32).
// MODE 2: fp32 -> Cout with coef (1/(1+row)) epilogue; z batched via strides.
#define PITCH 80
#define ABUF  10240
#define TBUF  20480

template<int MODE>
__global__ void __launch_bounds__(256)
mma_core(const __nv_bfloat16* __restrict__ A, long lda,
         const __nv_bfloat16* __restrict__ B, long ldb,
         int kTiles,
         __nv_bfloat16* __restrict__ Eout, float* __restrict__ denPart,
         float* __restrict__ Cout, long ldC,
         int zdiv, long sAlo, long sAhi, long sBlo, long sBhi, long sClo, long sChi)
{
    __shared__ char smem[2*TBUF];
    const uint32_t sb = smem_u32(smem);
    const int tid = threadIdx.x, lane = tid & 31, wid = tid >> 5;
    const int wm = wid & 1, wn = wid >> 1;
    const int wmBase = wm * 64, wnBase = wn * 32;
    const int rowBase = blockIdx.y << 7, colBase = blockIdx.x << 7;
    long k0base = 0;
    if (MODE == 1){
        k0base = (long)blockIdx.z * kTiles * 32;
        Cout += (size_t)blockIdx.z * ((size_t)Rc*Dc);
    } else if (MODE == 2){
        int lo = blockIdx.z % zdiv, hi = blockIdx.z / zdiv;
        A += (size_t)lo * sAlo + (size_t)hi * sAhi;
        B += (size_t)lo * sBlo + (size_t)hi * sBhi;
        Cout += (size_t)lo * sClo + (size_t)hi * sChi;
    }

    float acc[4][4][4];
#pragma unroll
    for (int mt = 0; mt < 4; mt++)
#pragma unroll
        for (int nt = 0; nt < 4; nt++)
#pragma unroll
            for (int q = 0; q < 4; q++) acc[mt][nt][q] = 0.f;

    const int ar = lane & 15;
    const int akof = (lane >> 4) * 8;
    const int bn = (lane & 7) + ((lane & 16) ? 8 : 0);
    const int bkof = ((lane >> 3) & 1) * 8;

    auto load = [&](int buf, long k0){
        uint32_t base = sb + buf*TBUF;
#pragma unroll
        for (int i = 0; i < 2; i++){
            int c = tid + i*256; int r = c >> 2, s = c & 3;
            cp16(base + r*PITCH + s*16, A + (size_t)(rowBase + r)*lda + k0 + s*8);
        }
#pragma unroll
        for (int i = 0; i < 2; i++){
            int c = tid + i*256; int r = c >> 2, s = c & 3;
            cp16(base + ABUF + r*PITCH + s*16, B + (size_t)(colBase + r)*ldb + k0 + s*8);
        }
        cp_commit();
    };

    load(0, k0base);
    for (int t = 0; t < kTiles; t++){
        if (t + 1 < kTiles){ load((t+1)&1, k0base + (long)(t+1)*32); cp_wait<1>(); }
        else cp_wait<0>();
        __syncthreads();
        uint32_t base = sb + (t&1)*TBUF;
#pragma unroll
        for (int kk = 0; kk < 2; kk++){
            uint32_t a[4][4], b[2][4];
            uint32_t aCol = (uint32_t)((kk*16 + akof) * 2);
            uint32_t bCol = (uint32_t)((kk*16 + bkof) * 2);
#pragma unroll
            for (int mt = 0; mt < 4; mt++)
                ldm_x4(a[mt][0], a[mt][1], a[mt][2], a[mt][3],
                       base + (uint32_t)(wmBase + mt*16 + ar)*PITCH + aCol);
#pragma unroll
            for (int j = 0; j < 2; j++)
                ldm_x4(b[j][0], b[j][1], b[j][2], b[j][3],
                       base + ABUF + (uint32_t)(wnBase + j*16 + bn)*PITCH + bCol);
#pragma unroll
            for (int mt = 0; mt < 4; mt++)
#pragma unroll
                for (int nt = 0; nt < 4; nt++)
                    mma16816(acc[mt][nt], a[mt][0], a[mt][1], a[mt][2], a[mt][3],
                             b[nt>>1][(nt&1)*2], b[nt>>1][(nt&1)*2 + 1]);
        }
        __syncthreads();
    }

    int cq = (lane & 3) * 2;
    if (MODE == 0){
        float* denm = (float*)smem;
#pragma unroll
        for (int mt = 0; mt < 4; mt++){
            int lr0 = wmBase + mt*16 + (lane >> 2);
            int r0 = rowBase + lr0;
            float s0 = 0.f, s1 = 0.f;
#pragma unroll
            for (int nt = 0; nt < 4; nt++){
                int col = colBase + wnBase + nt*8 + cq;
                float e0 = __expf(fminf(acc[mt][nt][0], 70.f));
                float e1 = __expf(fminf(acc[mt][nt][1], 70.f));
                float e2 = __expf(fminf(acc[mt][nt][2], 70.f));
                float e3 = __expf(fminf(acc[mt][nt][3], 70.f));
                s0 += e0 + e1; s1 += e2 + e3;
                *(__nv_bfloat162*)(Eout + (size_t)r0*Vc + col) =
                    __float22bfloat162_rn(make_float2(e0, e1));
                *(__nv_bfloat162*)(Eout + (size_t)(r0+8)*Vc + col) =
                    __float22bfloat162_rn(make_float2(e2, e3));
            }
            s0 += __shfl_xor_sync(0xffffffffu, s0, 1);
            s0 += __shfl_xor_sync(0xffffffffu, s0, 2);
            s1 += __shfl_xor_sync(0xffffffffu, s1, 1);
            s1 += __shfl_xor_sync(0xffffffffu, s1, 2);
            if ((lane & 3) == 0){
                denm[lr0*4 + wn] = s0;
                denm[(lr0+8)*4 + wn] = s1;
            }
        }
        __syncthreads();
        if (tid < 128){
            float d = denm[tid*4] + denm[tid*4+1] + denm[tid*4+2] + denm[tid*4+3];
            denPart[(size_t)blockIdx.x * Rc + rowBase + tid] = d;
        }
    } else {
#pragma unroll
        for (int mt = 0; mt < 4; mt++){
            int r0 = rowBase + wmBase + mt*16 + (lane >> 2);
            float c0 = 1.f, c1 = 1.f;
            if (MODE == 2){
                c0 = 1.0f / (1.0f + (float)r0);
                c1 = 1.0f / (1.0f + (float)(r0 + 8));
            }
#pragma unroll
            for (int nt = 0; nt < 4; nt++){
                int col = colBase + wnBase + nt*8 + cq;
                *(float2*)(Cout + (size_t)r0*ldC + col) =
                    make_float2(acc[mt][nt][0]*c0, acc[mt][nt][1]*c0);
                *(float2*)(Cout + (size_t)(r0+8)*ldC + col) =
                    make_float2(acc[mt][nt][2]*c1, acc[mt][nt][3]*c1);
            }
        }
    }
}

// =================== fp32 SGEMM (QK / krn only) ===================
#define EPI_NONE 0
#define EPI_ATTN 1
#define BM 128
#define BN 128
#define BK 8

__global__ void __launch_bounds__(256)
sgemm_nn(int M, int N, int K,
         const float* __restrict__ A, int lda,
         const float* __restrict__ B, int ldb,
         float* __restrict__ C, int ldc,
         int epi, float scale, int zdiv,
         long sAlo, long sAhi, long sBlo, long sBhi, long sClo, long sChi)
{
    __shared__ float As[BK][BM];
    __shared__ float Bs[BK][BN];
    int z = blockIdx.z;
    {
        int lo = z % zdiv, hi = z / zdiv;
        A += (size_t)lo * sAlo + (size_t)hi * sAhi;
        B += (size_t)lo * sBlo + (size_t)hi * sBhi;
        C += (size_t)lo * sClo + (size_t)hi * sChi;
    }
    const int tid = threadIdx.x;
    const int tx = tid & 15, ty = tid >> 4;
    const int rowBase = blockIdx.y * BM, colBase = blockIdx.x * BN;
    const int aRow = tid >> 1,  aCol = (tid & 1) << 2;
    const int bRow = tid >> 5,  bCol = (tid & 31) << 2;

    float acc[8][8];
#pragma unroll
    for (int i = 0; i < 8; i++)
#pragma unroll
        for (int j = 0; j < 8; j++) acc[i][j] = 0.f;

    for (int k0 = 0; k0 < K; k0 += BK) {
        float4 av = *(const float4*)(A + (size_t)(rowBase + aRow) * lda + k0 + aCol);
        As[aCol+0][aRow] = av.x; As[aCol+1][aRow] = av.y;
        As[aCol+2][aRow] = av.z; As[aCol+3][aRow] = av.w;
        float4 bv = *(const float4*)(B + (size_t)(k0 + bRow) * ldb + colBase + bCol);
        *(float4*)&Bs[bRow][bCol] = bv;
        __syncthreads();
#pragma unroll
        for (int kk = 0; kk < BK; kk++) {
            float a[8], b[8];
            *(float4*)&a[0] = *(const float4*)&As[kk][ty*8];
            *(float4*)&a[4] = *(const float4*)&As[kk][ty*8+4];
            *(float4*)&b[0] = *(const float4*)&Bs[kk][tx*8];
            *(float4*)&b[4] = *(const float4*)&Bs[kk][tx*8+4];
#pragma unroll
            for (int i = 0; i < 8; i++)
#pragma unroll
                for (int j = 0; j < 8; j++) acc[i][j] = fmaf(a[i], b[j], acc[i][j]);
        }
        __syncthreads();
    }
#pragma unroll
    for (int i = 0; i < 8; i++) {
        int r = rowBase + ty*8 + i;
#pragma unroll
        for (int j = 0; j < 8; j++) {
            int c = colBase + tx*8 + j;
            C[(size_t)r * ldc + c] = acc[i][j];
        }
    }
}

__global__ void __launch_bounds__(256)
sgemm_nt(int M, int N, int K,
         const float* __restrict__ A, int lda,
         const float* __restrict__ B, int ldb,
         float* __restrict__ C, int ldc,
         int epi, float scale, int zdiv,
         long sAlo, long sAhi, long sBlo, long sBhi, long sClo, long sChi)
{
    __shared__ float As[BK][BM];
    __shared__ float Bs[BK][BN];
    int z = blockIdx.z;
    {
        int lo = z % zdiv, hi = z / zdiv;
        A += (size_t)lo * sAlo + (size_t)hi * sAhi;
        B += (size_t)lo * sBlo + (size_t)hi * sBhi;
        C += (size_t)lo * sClo + (size_t)hi * sChi;
    }
    const int tid = threadIdx.x;
    const int tx = tid & 15, ty = tid >> 4;
    const int rowBase = blockIdx.y * BM, colBase = blockIdx.x * BN;
    const int aRow = tid >> 1, aCol = (tid & 1) << 2;
    const int bN   = tid >> 1, bK   = (tid & 1) << 2;

    float acc[8][8];
#pragma unroll
    for (int i = 0; i < 8; i++)
#pragma unroll
        for (int j = 0; j < 8; j++) acc[i][j] = 0.f;

    for (int k0 = 0; k0 < K; k0 += BK) {
        float4 av = *(const float4*)(A + (size_t)(rowBase + aRow) * lda + k0 + aCol);
        As[aCol+0][aRow] = av.x; As[aCol+1][aRow] = av.y;
        As[aCol+2][aRow] = av.z; As[aCol+3][aRow] = av.w;
        float4 bv = *(const float4*)(B + (size_t)(colBase + bN) * ldb + k0 + bK);
        Bs[bK+0][bN] = bv.x; Bs[bK+1][bN] = bv.y;
        Bs[bK+2][bN] = bv.z; Bs[bK+3][bN] = bv.w;
        __syncthreads();
#pragma unroll
        for (int kk = 0; kk < BK; kk++) {
            float a[8], b[8];
            *(float4*)&a[0] = *(const float4*)&As[kk][ty*8];
            *(float4*)&a[4] = *(const float4*)&As[kk][ty*8+4];
            *(float4*)&b[0] = *(const float4*)&Bs[kk][tx*8];
            *(float4*)&b[4] = *(const float4*)&Bs[kk][tx*8+4];
#pragma unroll
            for (int i = 0; i < 8; i++)
#pragma unroll
                for (int j = 0; j < 8; j++) acc[i][j] = fmaf(a[i], b[j], acc[i][j]);
        }
        __syncthreads();
    }
#pragma unroll
    for (int i = 0; i < 8; i++) {
        int r = rowBase + ty*8 + i;
#pragma unroll
        for (int j = 0; j < 8; j++) {
            int c = colBase + tx*8 + j;
            float v = acc[i][j];
            if (epi == EPI_ATTN) {
                v *= scale;
                v = fminf(10.f, fmaxf(-10.f, v));
                if (c > r) v = -INFINITY;
            }
            C[(size_t)r * ldc + c] = v;
        }
    }
}

// ---------------- reductions / elementwise ----------------
__device__ __forceinline__ float warpSum(float v) {
#pragma unroll
    for (int o = 16; o; o >>= 1) v += __shfl_xor_sync(0xffffffffu, v, o);
    return v;
}
__device__ __forceinline__ float warpMax(float v) {
#pragma unroll
    for (int o = 16; o; o >>= 1) v = fmaxf(v, __shfl_xor_sync(0xffffffffu, v, o));
    return v;
}

__global__ void ln_rows(const float* __restrict__ base, const int* __restrict__ idx,
                        const float* __restrict__ g, float* __restrict__ dst,
                        long rowStride)
{
    int row = blockIdx.x;
    const float* src = base + (idx ? (size_t)idx[row] * rowStride
                                   : (size_t)row * rowStride);
    int tid = threadIdx.x, lane = tid & 31, w = tid >> 5;
    __shared__ float sb[8];
    float v0 = src[tid], v1 = src[tid + 256];
    float s = warpSum(v0 + v1);
    if (lane == 0) sb[w] = s;
    __syncthreads();
    float tot = 0.f;
#pragma unroll
    for (int i = 0; i < 8; i++) tot += sb[i];
    float m = tot * (1.f / 512.f);
    float a0 = v0 - m, a1 = v1 - m;
    __syncthreads();
    float q = warpSum(a0*a0 + a1*a1);
    if (lane == 0) sb[w] = q;
    __syncthreads();
    float var = 0.f;
#pragma unroll
    for (int i = 0; i < 8; i++) var += sb[i];
    var *= (1.f / 512.f);
    float inv = rsqrtf(var + 1e-5f);
    float* dr = dst + (size_t)row * 512;
    dr[tid]       = a0 * inv * g[tid];
    dr[tid + 256] = a1 * inv * g[tid + 256];
}

__global__ void softmax_rows(float* __restrict__ data, int ncol)
{
    float* row = data + (size_t)blockIdx.x * ncol;
    __shared__ float sb[8];
    int tid = threadIdx.x, lane = tid & 31, w = tid >> 5;
    float m = -INFINITY;
    for (int c = tid; c < ncol; c += 256) m = fmaxf(m, row[c]);
    m = warpMax(m);
    if (lane == 0) sb[w] = m;
    __syncthreads();
    float bm = sb[0];
#pragma unroll
    for (int i = 1; i < 8; i++) bm = fmaxf(bm, sb[i]);
    __syncthreads();
    float s = 0.f;
    for (int c = tid; c < ncol; c += 256) s += __expf(row[c] - bm);
    s = warpSum(s);
    if (lane == 0) sb[w] = s;
    __syncthreads();
    float bs = 0.f;
#pragma unroll
    for (int i = 0; i < 8; i++) bs += sb[i];
    float inv = 1.f / bs;
    for (int c = tid; c < ncol; c += 256) row[c] = __expf(row[c] - bm) * inv;
}

__global__ void col_mean_part(const float* __restrict__ wte)
{
    int d = blockIdx.x * 128 + threadIdx.x;
    int z = blockIdx.y;
    float s = 0.f;
    int v0 = z * 1000;
    for (int v = v0; v < v0 + 1000; v++) s += wte[(size_t)v * Dc + d];
    d_cmeanp[z * Dc + d] = s;
}
__global__ void col_mean_reduce()
{
    int d = blockIdx.x * 128 + threadIdx.x;
    float s = 0.f;
#pragma unroll
    for (int z = 0; z < 32; z++) s += d_cmeanp[z * Dc + d];
    d_cmean[d] = s * (1.f / 32000.f);
}

__global__ void vm_mean_k()
{
    int i = blockIdx.x * 256 + threadIdx.x;
    d_vm[i] = d_e[i] - d_cmean[i & (Dc - 1)];
}

__global__ void den_reduce()
{
    int r = blockIdx.x * 256 + threadIdx.x;
    float s = 0.f;
    for (int x = 0; x < Vc/128; x++) s += d_denp[(size_t)x * Rc + r];
    d_den[r] = s;
}

__global__ void vm_combine()
{
    int i = blockIdx.x * 256 + threadIdx.x;
    int r = i >> 9;
    float num = 0.f;
#pragma unroll
    for (int z = 0; z < NSPLIT; z++) num += d_part[(size_t)z * ((size_t)Rc*Dc) + i];
    d_vm[i] = d_e[i] - num / d_den[r];
}

// fk += sum of 4 split-K partials (W_o)
__global__ void fk_combine()
{
    int i = blockIdx.x * 256 + threadIdx.x;
    float s = d_part[i]
            + d_part[(size_t)(Rc*Dc) + i]
            + d_part[2*(size_t)(Rc*Dc) + i]
            + d_part[3*(size_t)(Rc*Dc) + i];
    d_fk[i] += s;
}

__global__ void f2bf(const float* __restrict__ in, __nv_bfloat16* __restrict__ out)
{
    size_t i = (size_t)blockIdx.x * 256 + threadIdx.x;
    float2 v = ((const float2*)in)[i];
    ((__nv_bfloat162*)out)[i] = __float22bfloat162_rn(v);
}

__global__ void transpose_wte(const float* __restrict__ w, __nv_bfloat16* __restrict__ o)
{
    __shared__ float t[32][33];
    int v0 = blockIdx.x * 32, d0 = blockIdx.y * 32;
    int tx = threadIdx.x, ty = threadIdx.y;
    for (int i = ty; i < 32; i += 8) t[i][tx] = w[(size_t)(v0 + i) * Dc + d0 + tx];
    __syncthreads();
    for (int i = ty; i < 32; i += 8)
        o[(size_t)(d0 + i) * Vc + v0 + tx] = __float2bfloat16(t[tx][i]);
}

// ---- split-bf16 builders ----
// krn3[h][s][k]: k=t -> hi, k=512+t -> hi, k=1024+t -> lo
__global__ void krn3_build()
{
    int i = blockIdx.x * 256 + threadIdx.x;       // over Hc*Sc*Sc
    int t = i & 511;
    int hs = i >> 9;                              // h*512 + s
    float x = d_krn[i];
    __nv_bfloat16 hi = __float2bfloat16(x);
    __nv_bfloat16 lo = __float2bfloat16(x - __bfloat162float(hi));
    __nv_bfloat16* row = d_krn3 + (size_t)hs * K3;
    row[t] = hi; row[512 + t] = hi; row[1024 + t] = lo;
}

// vm3t[b][d][k]: k=t -> hi, k=512+t -> lo, k=1024+t -> hi  (transposed from vm[b][t][d])
__global__ void vm3t_build()
{
    __shared__ float tl[32][33];
    int b = blockIdx.z;
    int t0 = blockIdx.x * 32, d0 = blockIdx.y * 32;
    int tx = threadIdx.x, ty = threadIdx.y;
    const float* src = d_vm + (size_t)b * Sc * Dc;
    for (int i = ty; i < 32; i += 8) tl[i][tx] = src[(size_t)(t0 + i) * Dc + d0 + tx];
    __syncthreads();
    __nv_bfloat16* dst = d_vm3t + (size_t)b * Dc * K3;
    for (int i = ty; i < 32; i += 8){
        float x = tl[tx][i];                      // vm[b][t0+tx][d0+i]
        __nv_bfloat16 hi = __float2bfloat16(x);
        __nv_bfloat16 lo = __float2bfloat16(x - __bfloat162float(hi));
        __nv_bfloat16* row = dst + (size_t)(d0 + i) * K3;
        row[t0 + tx] = hi; row[512 + t0 + tx] = lo; row[1024 + t0 + tx] = hi;
    }
}

// delta3[r][k]: k -> hi, 2048+k -> hi, 4096+k -> lo
__global__ void delta3_build()
{
    int i = blockIdx.x * 256 + threadIdx.x;       // over Rc*HDc
    int k = i & 2047, r = i >> 11;
    float x = d_delta[i];
    __nv_bfloat16 hi = __float2bfloat16(x);
    __nv_bfloat16 lo = __float2bfloat16(x - __bfloat162float(hi));
    __nv_bfloat16* row = d_delta3 + (size_t)r * K6;
    row[k] = hi; row[2048 + k] = hi; row[4096 + k] = lo;
}

// wo3t[n][k]: k -> hi, 2048+k -> lo, 4096+k -> hi
__global__ void wo3t_build(const float* __restrict__ W_o)
{
    int i = blockIdx.x * 256 + threadIdx.x;       // over Dc*HDc
    int k = i & 2047, n = i >> 11;
    float x = W_o[i];
    __nv_bfloat16 hi = __float2bfloat16(x);
    __nv_bfloat16 lo = __float2bfloat16(x - __bfloat162float(hi));
    __nv_bfloat16* row = d_wo3t + (size_t)n * K6;
    row[k] = hi; row[2048 + k] = lo; row[4096 + k] = hi;
}

__global__ void logits_kernel(const float* __restrict__ last,
                              const float* __restrict__ wte,
                              float* __restrict__ out)
{
    int w = threadIdx.x >> 5, lane = threadIdx.x & 31;
    int v = blockIdx.x * 8 + w;
    int b = blockIdx.y;
    const float* q = last + b * 512;
    const float* wr = wte + (size_t)v * 512;
    float s = 0.f;
#pragma unroll
    for (int d = lane; d < 512; d += 32) s = fmaf(q[d], wr[d], s);
    s = warpSum(s);
    if (lane == 0) out[(size_t)b * Vc + v] = s;
}

// ---------------- launch ----------------
extern "C" void kernel_launch(void* const* d_in, const int* in_sizes, int n_in,
                              void* d_out, int out_size)
{
    const int*   x   = (const int*)  d_in[0];
    const float* wte = (const float*)d_in[1];
    const float* wpe = (const float*)d_in[2];
    const float* g_e = (const float*)d_in[3];
    const float* g_p = (const float*)d_in[4];
    const float* g_f = (const float*)d_in[5];
    const float* W_q = (const float*)d_in[6];
    const float* W_k = (const float*)d_in[7];
    const float* W_o = (const float*)d_in[8];
    float* out = (float*)d_out;

    float *e, *p, *Q, *Kt, *krn, *fk, *vm, *delta, *part, *last, *denp;
    __nv_bfloat16 *E, *wte_bf, *wteT_bf, *fk_bf, *krn3, *vm3t, *delta3, *wo3t;
    cudaGetSymbolAddress((void**)&e,     d_e);
    cudaGetSymbolAddress((void**)&p,     d_p);
    cudaGetSymbolAddress((void**)&Q,     d_Q);
    cudaGetSymbolAddress((void**)&Kt,    d_Kt);
    cudaGetSymbolAddress((void**)&krn,   d_krn);
    cudaGetSymbolAddress((void**)&fk,    d_fk);
    cudaGetSymbolAddress((void**)&vm,    d_vm);
    cudaGetSymbolAddress((void**)&delta, d_delta);
    cudaGetSymbolAddress((void**)&part,  d_part);
    cudaGetSymbolAddress((void**)&last,  d_last);
    cudaGetSymbolAddress((void**)&denp,  d_denp);
    cudaGetSymbolAddress((void**)&E,       d_E);
    cudaGetSymbolAddress((void**)&wte_bf,  d_wte_bf);
    cudaGetSymbolAddress((void**)&wteT_bf, d_wteT_bf);
    cudaGetSymbolAddress((void**)&fk_bf,   d_fk_bf);
    cudaGetSymbolAddress((void**)&krn3,    d_krn3);
    cudaGetSymbolAddress((void**)&vm3t,    d_vm3t);
    cudaGetSymbolAddress((void**)&delta3,  d_delta3);
    cudaGetSymbolAddress((void**)&wo3t,    d_wo3t);

    const long SD = (long)Sc * Dc;
    const long SS = (long)Sc * Sc;
    const float attnScale = 0.044194173824159216f;  // 1/sqrt(512)

    // embeddings + positional LN
    ln_rows<<<Rc,   256>>>(wte, x, g_e, e, (long)Dc);
    ln_rows<<<Sc+1, 256>>>(wpe, nullptr, g_p, p, (long)Dc);

    // layer-0 ex_wte = column mean of wte
    col_mean_part<<<dim3(4, 32), 128>>>(wte);
    col_mean_reduce<<<4, 128>>>();

    // bf16 copies of wte + W_o split (once)
    f2bf<<<(Vc*Dc/2)/256, 256>>>(wte, wte_bf);
    transpose_wte<<<dim3(Vc/32, Dc/32), dim3(32, 8)>>>(wte, wteT_bf);
    wo3t_build<<<(Dc*HDc)/256, 256>>>(W_o);

    // Q/K/krn (fp32)
    sgemm_nn<<<dim3(4,4,4),256>>>(Sc,Dc,Dc, p+Dc,Dc, W_q,Dc, Q,Dc,
                                  EPI_NONE, 0.f, 1,
                                  0,0, 0,(long)Dc*Dc, 0,SD);
    sgemm_nn<<<dim3(4,4,4),256>>>(Sc,Dc,Dc, p,Dc, W_k,Dc, Kt,Dc,
                                  EPI_NONE, 0.f, 1,
                                  0,0, 0,(long)Dc*Dc, 0,SD);
    sgemm_nt<<<dim3(4,4,4),256>>>(Sc,Sc,Dc, Q,Dc, Kt,Dc, krn,Sc,
                                  EPI_ATTN, attnScale, 1,
                                  0,SD, 0,SD, 0,SS);
    softmax_rows<<<Hc*Sc, 256>>>(krn, Sc);
    krn3_build<<<(Hc*Sc*Sc)/256, 256>>>();

    cudaMemsetAsync(fk, 0, (size_t)Rc * Dc * sizeof(float), 0);

    for (int layer = 0; layer < 4; layer++) {
        if (layer == 0) {
            vm_mean_k<<<Rc*Dc/256, 256>>>();
        } else {
            // E = exp(f_k @ wte^T), fused row-sum partials
            f2bf<<<(Rc*Dc/2)/256, 256>>>(fk, fk_bf);
            mma_core<0><<<dim3(Vc/128, Rc/128, 1), 256>>>(
                fk_bf, (long)Dc, wte_bf, (long)Dc, Dc/32,
                E, denp, nullptr, 0, 1, 0,0,0,0,0,0);
            den_reduce<<<Rc/256, 256>>>();
            // num = E @ wte (split-K over 10 chunks)
            mma_core<1><<<dim3(Dc/128, Rc/128, NSPLIT), 256>>>(
                E, (long)Vc, wteT_bf, (long)Vc, (Vc/NSPLIT)/32,
                nullptr, nullptr, part, (long)Dc, 1, 0,0,0,0,0,0);
            vm_combine<<<Rc*Dc/256, 256>>>();
        }
        // split Vm -> vm3t
        vm3t_build<<<dim3(16,16,4), dim3(32,8)>>>();
        // delta[b,s,h,d] = coef * (krn3[h] @ vm3t[b]^T), z = b*4+h
        mma_core<2><<<dim3(4,4,16), 256>>>(
            krn3, (long)K3, vm3t, (long)K3, K3/32,
            nullptr, nullptr, delta, (long)HDc, 4,
            (long)Sc*K3, 0,                 // A: +h*S*K3
            0, (long)Dc*K3,                 // B: +b*D*K3
            (long)Dc, (long)Sc*HDc);        // C: +h*D + b*S*HD
        // split delta -> delta3, then f_k += delta @ W_o^T (4-way split-K)
        delta3_build<<<(Rc*HDc)/256, 256>>>();
        mma_core<1><<<dim3(Dc/128, Rc/128, 4), 256>>>(
            delta3, (long)K6, wo3t, (long)K6, K6/(4*32),
            nullptr, nullptr, part, (long)Dc, 1, 0,0,0,0,0,0);
        fk_combine<<<Rc*Dc/256, 256>>>();
    }

    ln_rows<<<Bc, 256>>>(fk + (size_t)(Sc-1)*Dc, nullptr, g_f, last, (long)Sc*Dc);
    logits_kernel<<<dim3(Vc/8, Bc), 256>>>(last, wte, out);
}